// round 7
// baseline (speedup 1.0000x reference)
#include <cuda_runtime.h>
#include <math.h>

// Problem constants
#define B_   2
#define S_   2048
#define D_   1024
#define H_   16
#define DK_  64
#define BS_  (B_ * S_)   // 4096

// ---------------------------------------------------------------------------
// Device scratch (no allocations allowed -> __device__ globals)
// ---------------------------------------------------------------------------
__device__ float g_Q[B_ * H_ * S_ * DK_];     // [B,H,S,DK]
__device__ float g_K[B_ * H_ * S_ * DK_];
__device__ float g_V[B_ * H_ * S_ * DK_];
__device__ float g_ctx[B_ * S_ * D_];         // [B,S,D] (== [B,S,H,DK])
__device__ float g_proj[B_ * S_ * D_];        // out-proj result before LN

// ---------------------------------------------------------------------------
// GEMM: Y[m][n] = sum_k A[m][k] * W[n][k] + bias[n]
//   A row-major [M x 1024], W row-major [1024 x 1024] (torch Linear weight)
//   MODE 0: store Y row-major [M x 1024]
//   MODE 1: store Y into [B,H,S,DK] layout (for Q/K/V)
// 128x128x8 tiles, 8x8 per thread, double-buffered smem. 256 threads.
// ---------------------------------------------------------------------------
template <int MODE>
__global__ __launch_bounds__(256, 2)
void gemm128(const float* __restrict__ A, const float* __restrict__ W,
             const float* __restrict__ bias, float* __restrict__ out)
{
    constexpr int K = D_;
    __shared__ float As[2][8][128];  // As[buf][k][m]
    __shared__ float Bs[2][8][128];  // Bs[buf][k][n]

    const int tid  = threadIdx.x;
    const int tx   = tid & 15;
    const int ty   = tid >> 4;
    const int row0 = blockIdx.y * 128;
    const int col0 = blockIdx.x * 128;

    const int lr = tid >> 1;         // 0..127 : tile row for loading
    const int lk = (tid & 1) << 2;   // 0 or 4 : k offset for loading

    const float* Aptr = A + (row0 + lr) * K + lk;
    const float* Wptr = W + (col0 + lr) * K + lk;

    float acc[8][8];
#pragma unroll
    for (int i = 0; i < 8; ++i)
#pragma unroll
        for (int j = 0; j < 8; ++j) acc[i][j] = 0.0f;

    // prologue: tile 0
    {
        float4 a4 = *(const float4*)Aptr;
        float4 b4 = *(const float4*)Wptr;
        As[0][lk + 0][lr] = a4.x; As[0][lk + 1][lr] = a4.y;
        As[0][lk + 2][lr] = a4.z; As[0][lk + 3][lr] = a4.w;
        Bs[0][lk + 0][lr] = b4.x; Bs[0][lk + 1][lr] = b4.y;
        Bs[0][lk + 2][lr] = b4.z; Bs[0][lk + 3][lr] = b4.w;
    }
    __syncthreads();

    constexpr int TILES = K / 8;   // 128
    for (int t = 0; t < TILES; ++t) {
        const int cur = t & 1;
        float4 na, nb;
        const bool has_next = (t + 1 < TILES);
        if (has_next) {
            na = *(const float4*)(Aptr + (t + 1) * 8);
            nb = *(const float4*)(Wptr + (t + 1) * 8);
        }
#pragma unroll
        for (int kk = 0; kk < 8; ++kk) {
            float a[8], b[8];
            *(float4*)(a)     = *(const float4*)&As[cur][kk][ty * 4];
            *(float4*)(a + 4) = *(const float4*)&As[cur][kk][64 + ty * 4];
            *(float4*)(b)     = *(const float4*)&Bs[cur][kk][tx * 4];
            *(float4*)(b + 4) = *(const float4*)&Bs[cur][kk][64 + tx * 4];
#pragma unroll
            for (int i = 0; i < 8; ++i)
#pragma unroll
                for (int j = 0; j < 8; ++j)
                    acc[i][j] += a[i] * b[j];
        }
        if (has_next) {
            const int nxt = cur ^ 1;
            As[nxt][lk + 0][lr] = na.x; As[nxt][lk + 1][lr] = na.y;
            As[nxt][lk + 2][lr] = na.z; As[nxt][lk + 3][lr] = na.w;
            Bs[nxt][lk + 0][lr] = nb.x; Bs[nxt][lk + 1][lr] = nb.y;
            Bs[nxt][lk + 2][lr] = nb.z; Bs[nxt][lk + 3][lr] = nb.w;
        }
        __syncthreads();
    }

    // epilogue: bias + store
    float bb[8];
    *(float4*)(bb)     = *(const float4*)&bias[col0 + tx * 4];
    *(float4*)(bb + 4) = *(const float4*)&bias[col0 + 64 + tx * 4];

#pragma unroll
    for (int ih = 0; ih < 2; ++ih) {
#pragma unroll
        for (int i = 0; i < 4; ++i) {
            const int m = row0 + ih * 64 + ty * 4 + i;
#pragma unroll
            for (int jh = 0; jh < 2; ++jh) {
                float4 v;
                v.x = acc[ih * 4 + i][jh * 4 + 0] + bb[jh * 4 + 0];
                v.y = acc[ih * 4 + i][jh * 4 + 1] + bb[jh * 4 + 1];
                v.z = acc[ih * 4 + i][jh * 4 + 2] + bb[jh * 4 + 2];
                v.w = acc[ih * 4 + i][jh * 4 + 3] + bb[jh * 4 + 3];
                const int c = col0 + jh * 64 + tx * 4;
                if (MODE == 0) {
                    *(float4*)&out[m * D_ + c] = v;
                } else {
                    const int b  = m >> 11;       // / S_
                    const int s  = m & (S_ - 1);
                    const int h  = c >> 6;        // / DK_
                    const int dk = c & 63;
                    *(float4*)&out[(((b * H_ + h) * S_) + s) * DK_ + dk] = v;
                }
            }
        }
    }
}

// ---------------------------------------------------------------------------
// Flash attention, fp32, 128-row Q tile x 64-col K tiles.
// 256 threads, thread (ty,tx) owns rows ty*8+i (8) and cols tx*4+j (4).
// smem (dynamic, 96 KB):
//   Qst [64][128]  (d-major)   32 KB
//   Kst [64][64]   (d-major)   16 KB
//   Vs  [64][64]   (row-major) 16 KB
//   Ps  [128][64]  (row-major) 32 KB
// 2 CTAs/SM (192 KB smem, <=128 regs).
// ---------------------------------------------------------------------------
__global__ __launch_bounds__(256, 2)
void attn128(const float* __restrict__ cplx, const float* __restrict__ cpen_p)
{
    extern __shared__ float sm[];
    float* Qst = sm;                    // [64][128]
    float* Kst = sm + 64 * 128;         // [64][64]
    float* Vs  = Kst + 64 * 64;         // [64][64]
    float* Ps  = Vs  + 64 * 64;         // [128][64]

    const int tid = threadIdx.x;
    const int tx  = tid & 15;
    const int ty  = tid >> 4;
    const int qt  = (gridDim.x - 1) - blockIdx.x;   // heavy tiles first
    const int bh  = blockIdx.y;
    const int b   = bh >> 4;   // / H_
    const int h   = bh & 15;
    const float cpen = __ldg(cpen_p);

    const float* Qg = g_Q + (size_t)bh * S_ * DK_;
    const float* Kg = g_K + (size_t)bh * S_ * DK_;
    const float* Vg = g_V + (size_t)bh * S_ * DK_;

    // ---- load Q tile transposed into Qst[d][r]; conflict-free stores ----
    {
        const int r  = tid & 127;            // 32 consecutive r per warp
        const int d0 = (tid >> 7) * 32;      // 0 or 32
        const float* src = Qg + (qt * 128 + r) * DK_ + d0;
#pragma unroll
        for (int q = 0; q < 8; ++q) {
            float4 v = *(const float4*)(src + q * 4);
            Qst[(d0 + q * 4 + 0) * 128 + r] = v.x;
            Qst[(d0 + q * 4 + 1) * 128 + r] = v.y;
            Qst[(d0 + q * 4 + 2) * 128 + r] = v.z;
            Qst[(d0 + q * 4 + 3) * 128 + r] = v.w;
        }
    }

    float m_i[8], l_i[8], acc[8][4];
#pragma unroll
    for (int i = 0; i < 8; ++i) {
        m_i[i] = -1e30f; l_i[i] = 0.0f;
#pragma unroll
        for (int j = 0; j < 4; ++j) acc[i][j] = 0.0f;
    }

    const int nkt = 2 * qt + 2;
    for (int kt = 0; kt < nkt; ++kt) {
        __syncthreads();   // prior iter done with Kst/Vs/Ps; Qst visible (iter 0)

        // ---- load K transposed (Kst[d][c]) and V (Vs[j][d]) ----
        {
            const int c  = tid & 63;            // 32 consecutive c per warp
            const int d0 = (tid >> 6) * 16;     // 0,16,32,48
            const float* ks = Kg + (kt * 64 + c) * DK_ + d0;
#pragma unroll
            for (int q = 0; q < 4; ++q) {
                float4 kv = *(const float4*)(ks + q * 4);
                Kst[(d0 + q * 4 + 0) * 64 + c] = kv.x;
                Kst[(d0 + q * 4 + 1) * 64 + c] = kv.y;
                Kst[(d0 + q * 4 + 2) * 64 + c] = kv.z;
                Kst[(d0 + q * 4 + 3) * 64 + c] = kv.w;
            }
            const int vr  = tid >> 2;           // 0..63
            const int vd0 = (tid & 3) * 16;
            const float* vsrc = Vg + (kt * 64 + vr) * DK_ + vd0;
#pragma unroll
            for (int q = 0; q < 4; ++q)
                *(float4*)&Vs[vr * 64 + vd0 + q * 4] = *(const float4*)(vsrc + q * 4);
        }
        __syncthreads();

        // ---- scores: S[8][4] = Q K^T ----
        float s[8][4];
#pragma unroll
        for (int i = 0; i < 8; ++i)
#pragma unroll
            for (int j = 0; j < 4; ++j) s[i][j] = 0.0f;

#pragma unroll 2
        for (int d = 0; d < 64; ++d) {
            float4 a0 = *(const float4*)&Qst[d * 128 + ty * 8];      // broadcast
            float4 a1 = *(const float4*)&Qst[d * 128 + ty * 8 + 4];  // broadcast
            float4 bk = *(const float4*)&Kst[d * 64 + tx * 4];
            float a[8] = {a0.x, a0.y, a0.z, a0.w, a1.x, a1.y, a1.z, a1.w};
            float bv[4] = {bk.x, bk.y, bk.z, bk.w};
#pragma unroll
            for (int i = 0; i < 8; ++i)
#pragma unroll
                for (int j = 0; j < 4; ++j)
                    s[i][j] += a[i] * bv[j];
        }

        // ---- scale + complexity penalty + causal mask ----
        {
            float4 cv = *(const float4*)&cplx[b * S_ + kt * 64 + tx * 4];
            float pen[4] = {cpen * cv.x, cpen * cv.y, cpen * cv.z, cpen * cv.w};
#pragma unroll
            for (int i = 0; i < 8; ++i)
#pragma unroll
                for (int j = 0; j < 4; ++j)
                    s[i][j] = s[i][j] * 0.125f - pen[j];
            if (kt >= 2 * qt) {           // (possibly) diagonal tile
                const int cb = kt * 64 + tx * 4;
                const int rb = qt * 128 + ty * 8;
#pragma unroll
                for (int i = 0; i < 8; ++i)
#pragma unroll
                    for (int j = 0; j < 4; ++j)
                        if (cb + j > rb + i) s[i][j] = -1e9f;
            }
        }

        // ---- online softmax + stage P into Ps (row-major) ----
#pragma unroll
        for (int i = 0; i < 8; ++i) {
            float mx = fmaxf(fmaxf(s[i][0], s[i][1]), fmaxf(s[i][2], s[i][3]));
#pragma unroll
            for (int off = 1; off < 16; off <<= 1)
                mx = fmaxf(mx, __shfl_xor_sync(0xffffffffu, mx, off, 16));
            const float nm = fmaxf(m_i[i], mx);
            const float alpha = __expf(m_i[i] - nm);
            m_i[i] = nm;
            float rs = 0.0f;
#pragma unroll
            for (int j = 0; j < 4; ++j) {
                s[i][j] = __expf(s[i][j] - nm);
                rs += s[i][j];
            }
#pragma unroll
            for (int off = 1; off < 16; off <<= 1)
                rs += __shfl_xor_sync(0xffffffffu, rs, off, 16);
            l_i[i] = l_i[i] * alpha + rs;
#pragma unroll
            for (int j = 0; j < 4; ++j) acc[i][j] *= alpha;
            *(float4*)&Ps[(ty * 8 + i) * 64 + tx * 4] =
                make_float4(s[i][0], s[i][1], s[i][2], s[i][3]);
        }
        __syncthreads();   // P visible

        // ---- ctx += P V  (j unrolled by 4; P loads are warp-broadcast) ----
#pragma unroll 4
        for (int j0 = 0; j0 < 64; j0 += 4) {
            float4 bv0 = *(const float4*)&Vs[(j0 + 0) * 64 + tx * 4];
            float4 bv1 = *(const float4*)&Vs[(j0 + 1) * 64 + tx * 4];
            float4 bv2 = *(const float4*)&Vs[(j0 + 2) * 64 + tx * 4];
            float4 bv3 = *(const float4*)&Vs[(j0 + 3) * 64 + tx * 4];
#pragma unroll
            for (int i = 0; i < 8; ++i) {
                float4 p = *(const float4*)&Ps[(ty * 8 + i) * 64 + j0];  // broadcast
                acc[i][0] += p.x * bv0.x + p.y * bv1.x + p.z * bv2.x + p.w * bv3.x;
                acc[i][1] += p.x * bv0.y + p.y * bv1.y + p.z * bv2.y + p.w * bv3.y;
                acc[i][2] += p.x * bv0.z + p.y * bv1.z + p.z * bv2.z + p.w * bv3.z;
                acc[i][3] += p.x * bv0.w + p.y * bv1.w + p.z * bv2.w + p.w * bv3.w;
            }
        }
    }

    // ---- epilogue ----
#pragma unroll
    for (int i = 0; i < 8; ++i) {
        const float inv = 1.0f / l_i[i];
        const int srow = qt * 128 + ty * 8 + i;
        float4 v = make_float4(acc[i][0] * inv, acc[i][1] * inv,
                               acc[i][2] * inv, acc[i][3] * inv);
        *(float4*)&g_ctx[((size_t)(b * S_ + srow)) * D_ + h * DK_ + tx * 4] = v;
    }
}

// ---------------------------------------------------------------------------
// LayerNorm over D=1024 with residual add: out = LN(g_proj + query)*g + b
// ---------------------------------------------------------------------------
__global__ __launch_bounds__(256)
void ln_resid(const float* __restrict__ resid, const float* __restrict__ gamma,
              const float* __restrict__ beta, float* __restrict__ out)
{
    __shared__ float rs[8], rq[8];
    const int row = blockIdx.x;
    const int tid = threadIdx.x;

    const float* xr = g_proj + (size_t)row * D_;
    const float* rr = resid  + (size_t)row * D_;

    float4 a = *(const float4*)&xr[tid * 4];
    float4 r = *(const float4*)&rr[tid * 4];
    float x0 = a.x + r.x, x1 = a.y + r.y, x2 = a.z + r.z, x3 = a.w + r.w;

    float s  = x0 + x1 + x2 + x3;
    float sq = x0 * x0 + x1 * x1 + x2 * x2 + x3 * x3;
#pragma unroll
    for (int off = 16; off >= 1; off >>= 1) {
        s  += __shfl_xor_sync(0xffffffffu, s,  off);
        sq += __shfl_xor_sync(0xffffffffu, sq, off);
    }
    const int wid = tid >> 5;
    if ((tid & 31) == 0) { rs[wid] = s; rq[wid] = sq; }
    __syncthreads();
    float tot = 0.0f, totq = 0.0f;
#pragma unroll
    for (int w = 0; w < 8; ++w) { tot += rs[w]; totq += rq[w]; }

    const float mean = tot * (1.0f / D_);
    const float var  = totq * (1.0f / D_) - mean * mean;
    const float rstd = rsqrtf(var + 1e-5f);

    float4 g = *(const float4*)&gamma[tid * 4];
    float4 be = *(const float4*)&beta[tid * 4];
    float4 o;
    o.x = (x0 - mean) * rstd * g.x + be.x;
    o.y = (x1 - mean) * rstd * g.y + be.y;
    o.z = (x2 - mean) * rstd * g.z + be.z;
    o.w = (x3 - mean) * rstd * g.w + be.w;
    *(float4*)&out[(size_t)row * D_ + tid * 4] = o;
}

// ---------------------------------------------------------------------------
// kernel_launch
// ---------------------------------------------------------------------------
extern "C" void kernel_launch(void* const* d_in, const int* in_sizes, int n_in,
                              void* d_out, int out_size)
{
    (void)in_sizes; (void)n_in; (void)out_size;

    const float* query = (const float*)d_in[0];
    const float* key   = (const float*)d_in[1];
    const float* value = (const float*)d_in[2];
    const float* cplx  = (const float*)d_in[3];
    // d_in[4] = mask (bool tril) — deterministic, applied analytically
    const float* wq = (const float*)d_in[5];
    const float* bq = (const float*)d_in[6];
    const float* wk = (const float*)d_in[7];
    const float* bk = (const float*)d_in[8];
    const float* wv = (const float*)d_in[9];
    const float* bv = (const float*)d_in[10];
    const float* wo = (const float*)d_in[11];
    const float* bo = (const float*)d_in[12];
    const float* lng = (const float*)d_in[13];
    const float* lnb = (const float*)d_in[14];
    const float* cpen = (const float*)d_in[15];
    float* out = (float*)d_out;

    void *pQ, *pK, *pV, *pCtx, *pProj;
    cudaGetSymbolAddress(&pQ,   g_Q);
    cudaGetSymbolAddress(&pK,   g_K);
    cudaGetSymbolAddress(&pV,   g_V);
    cudaGetSymbolAddress(&pCtx, g_ctx);
    cudaGetSymbolAddress(&pProj, g_proj);

    // Allow 96 KB dynamic smem for attn128 (idempotent; host-side, capture-safe)
    const int ATTN_SMEM = (64 * 128 + 64 * 64 + 64 * 64 + 128 * 64) * 4;  // 98304
    cudaFuncSetAttribute(attn128, cudaFuncAttributeMaxDynamicSharedMemorySize,
                         ATTN_SMEM);

    dim3 gg(D_ / 128, BS_ / 128);   // (8, 32)

    // Q/K/V projections -> [B,H,S,DK]
    gemm128<1><<<gg, 256>>>(query, wq, bq, (float*)pQ);
    gemm128<1><<<gg, 256>>>(key,   wk, bk, (float*)pK);
    gemm128<1><<<gg, 256>>>(value, wv, bv, (float*)pV);

    // Flash attention -> g_ctx [B,S,D]
    dim3 ga(S_ / 128, B_ * H_);     // (16, 32)
    attn128<<<ga, 256, ATTN_SMEM>>>(cplx, cpen);

    // Output projection -> g_proj [B,S,D]
    gemm128<0><<<gg, 256>>>((const float*)pCtx, wo, bo, (float*)pProj);

    // Residual + LayerNorm -> d_out
    ln_resid<<<BS_, 256>>>(query, lng, lnb, out);
}

// round 9
// speedup vs baseline: 1.6046x; 1.6046x over previous
#include <cuda_runtime.h>
#include <math.h>
#include <stdint.h>

// Problem constants
#define B_   2
#define S_   2048
#define D_   1024
#define H_   16
#define DK_  64
#define BS_  (B_ * S_)   // 4096

// ---------------------------------------------------------------------------
// Device scratch (no allocations allowed -> __device__ globals)
// ---------------------------------------------------------------------------
__device__ float g_Q[B_ * H_ * S_ * DK_];     // [B,H,S,DK]
__device__ float g_K[B_ * H_ * S_ * DK_];
__device__ float g_V[B_ * H_ * S_ * DK_];
__device__ float g_ctx[B_ * S_ * D_];         // [B,S,D]
__device__ float g_proj[B_ * S_ * D_];        // out-proj result before LN

// ---------------------------------------------------------------------------
// tf32 helpers
// ---------------------------------------------------------------------------
__device__ __forceinline__ uint32_t f2tf(float f) {
    uint32_t u;
    asm("cvt.rna.tf32.f32 %0, %1;" : "=r"(u) : "f"(f));
    return u;
}
__device__ __forceinline__ uint4 f2tf4(float4 v) {
    uint4 u;
    u.x = f2tf(v.x); u.y = f2tf(v.y); u.z = f2tf(v.z); u.w = f2tf(v.w);
    return u;
}
// D(16x8,f32) += A(16x8,tf32,row) * B(8x8,tf32,col)
__device__ __forceinline__ void mma_tf32(float& d0, float& d1, float& d2, float& d3,
                                         uint32_t a0, uint32_t a1, uint32_t a2, uint32_t a3,
                                         uint32_t b0, uint32_t b1) {
    asm volatile(
        "mma.sync.aligned.m16n8k8.row.col.f32.tf32.tf32.f32 "
        "{%0,%1,%2,%3}, {%4,%5,%6,%7}, {%8,%9}, {%0,%1,%2,%3};\n"
        : "+f"(d0), "+f"(d1), "+f"(d2), "+f"(d3)
        : "r"(a0), "r"(a1), "r"(a2), "r"(a3), "r"(b0), "r"(b1));
}

// ---------------------------------------------------------------------------
// tf32 tensor-core GEMM: Y[m][n] = sum_k A[m][k]*W[n][k] + bias[n]
//   A [M x 1024] row-major fp32, W [1024 x 1024] row-major fp32.
//   MODE 0: Y row-major [M x 1024];  MODE 1: Y scattered to [B,H,S,DK].
// CTA 128x128, 256 thr, 8 warps (2x4), warp tile 64x32 (4 m16 x 4 n8).
// k-chunks of 16, double-buffered smem, pitch 20 (conflict-free frag loads).
// ---------------------------------------------------------------------------
#define GP 20   // smem pitch (16 data + 4 pad)

template <int MODE>
__global__ __launch_bounds__(256, 2)
void gemm_tc(const float* __restrict__ A, const float* __restrict__ W,
             const float* __restrict__ bias, float* __restrict__ out)
{
    __shared__ uint32_t As[2][128 * GP];
    __shared__ uint32_t Bs[2][128 * GP];

    const int tid  = threadIdx.x;
    const int lane = tid & 31;
    const int w    = tid >> 5;
    const int wm   = w & 1;          // 0..1  (row half)
    const int wn   = w >> 1;         // 0..3  (col quarter)
    const int row0 = blockIdx.y * 128;
    const int col0 = blockIdx.x * 128;

    const int r = lane >> 2;         // 0..7
    const int j = lane & 3;          // 0..3

    // loader mapping: thread -> (row, k-offset within 16-chunk)
    const int lrow = tid & 127;
    const int lkq  = (tid >> 7) << 3;   // 0 or 8

    const float* Aptr = A + (size_t)(row0 + lrow) * D_ + lkq;
    const float* Wptr = W + (size_t)(col0 + lrow) * D_ + lkq;
    uint32_t* AsRow = &As[0][0];   // indexed with buf offset later
    uint32_t* BsRow = &Bs[0][0];
    const int sbase = lrow * GP + lkq;

    float acc[4][4][4];
#pragma unroll
    for (int mt = 0; mt < 4; ++mt)
#pragma unroll
        for (int nt = 0; nt < 4; ++nt)
#pragma unroll
            for (int c = 0; c < 4; ++c) acc[mt][nt][c] = 0.0f;

    // prologue: stage chunk 0
    {
        float4 a0 = *(const float4*)(Aptr + 0);
        float4 a1 = *(const float4*)(Aptr + 4);
        float4 b0 = *(const float4*)(Wptr + 0);
        float4 b1 = *(const float4*)(Wptr + 4);
        *(uint4*)&As[0][sbase + 0] = f2tf4(a0);
        *(uint4*)&As[0][sbase + 4] = f2tf4(a1);
        *(uint4*)&Bs[0][sbase + 0] = f2tf4(b0);
        *(uint4*)&Bs[0][sbase + 4] = f2tf4(b1);
    }
    __syncthreads();

    const int arow_base = (wm * 64 + r) * GP;     // + mt*16*GP (+8*GP)
    const int brow_base = (wn * 32 + r) * GP;     // + nt*8*GP

    constexpr int TILES = D_ / 16;   // 64
    for (int t = 0; t < TILES; ++t) {
        const int cur = t & 1;
        float4 pa0, pa1, pb0, pb1;
        const bool has_next = (t + 1 < TILES);
        if (has_next) {
            pa0 = *(const float4*)(Aptr + (t + 1) * 16 + 0);
            pa1 = *(const float4*)(Aptr + (t + 1) * 16 + 4);
            pb0 = *(const float4*)(Wptr + (t + 1) * 16 + 0);
            pb1 = *(const float4*)(Wptr + (t + 1) * 16 + 4);
        }
        const uint32_t* Ab = &As[cur][0];
        const uint32_t* Bb = &Bs[cur][0];
#pragma unroll
        for (int s = 0; s < 2; ++s) {
            const int k = s * 8 + j;
            uint32_t af[4][4];
#pragma unroll
            for (int mt = 0; mt < 4; ++mt) {
                const int base = arow_base + mt * 16 * GP;
                af[mt][0] = Ab[base + k];
                af[mt][1] = Ab[base + 8 * GP + k];
                af[mt][2] = Ab[base + k + 4];
                af[mt][3] = Ab[base + 8 * GP + k + 4];
            }
#pragma unroll
            for (int nt = 0; nt < 4; ++nt) {
                const int base = brow_base + nt * 8 * GP;
                uint32_t b0 = Bb[base + k];
                uint32_t b1 = Bb[base + k + 4];
#pragma unroll
                for (int mt = 0; mt < 4; ++mt)
                    mma_tf32(acc[mt][nt][0], acc[mt][nt][1], acc[mt][nt][2], acc[mt][nt][3],
                             af[mt][0], af[mt][1], af[mt][2], af[mt][3], b0, b1);
            }
        }
        if (has_next) {
            const int nxt = cur ^ 1;
            *(uint4*)&As[nxt][sbase + 0] = f2tf4(pa0);
            *(uint4*)&As[nxt][sbase + 4] = f2tf4(pa1);
            *(uint4*)&Bs[nxt][sbase + 0] = f2tf4(pb0);
            *(uint4*)&Bs[nxt][sbase + 4] = f2tf4(pb1);
        }
        __syncthreads();
    }

    // epilogue: bias + store (float2 per c-pair)
#pragma unroll
    for (int mt = 0; mt < 4; ++mt) {
        const int gr = row0 + wm * 64 + mt * 16 + r;
#pragma unroll
        for (int nt = 0; nt < 4; ++nt) {
            const int gc = col0 + wn * 32 + nt * 8 + 2 * j;
            const float2 bb = *(const float2*)&bias[gc];
            float2 v0 = make_float2(acc[mt][nt][0] + bb.x, acc[mt][nt][1] + bb.y);
            float2 v1 = make_float2(acc[mt][nt][2] + bb.x, acc[mt][nt][3] + bb.y);
            if (MODE == 0) {
                *(float2*)&out[(size_t)gr * D_ + gc]       = v0;
                *(float2*)&out[(size_t)(gr + 8) * D_ + gc] = v1;
            } else {
                const int h  = gc >> 6;
                const int dk = gc & 63;
                const int b0i = gr >> 11, s0 = gr & (S_ - 1);
                const int gr1 = gr + 8;
                const int b1i = gr1 >> 11, s1 = gr1 & (S_ - 1);
                *(float2*)&out[(((size_t)(b0i * H_ + h) * S_) + s0) * DK_ + dk] = v0;
                *(float2*)&out[(((size_t)(b1i * H_ + h) * S_) + s1) * DK_ + dk] = v1;
            }
        }
    }
}

// ---------------------------------------------------------------------------
// Flash attention, tf32 tensor cores.
// CTA: 128 thr (4 warps), Q-tile 64 rows, K-tile 64 keys. Warp w owns rows
// w*16 .. w*16+15 (one m16 slice). smem pitch 68 (conflict-free frags):
//   Qs[64][68]  Q[row][d]      (tf32)
//   Ks[64][68]  K[key][d]      (tf32)
//   Vt[64][68]  V^T[d][key]    (tf32)
//   Ps[64][68]  P[row][key]    (tf32, warp-private row slices)
// ---------------------------------------------------------------------------
#define AP 68

__global__ __launch_bounds__(128, 3)
void attn_tc(const float* __restrict__ cplx, const float* __restrict__ cpen_p)
{
    extern __shared__ uint32_t smem[];
    uint32_t* Qs = smem;                 // 64*68
    uint32_t* Ks = Qs + 64 * AP;
    uint32_t* Vt = Ks + 64 * AP;
    uint32_t* Ps = Vt + 64 * AP;

    const int tid  = threadIdx.x;
    const int lane = tid & 31;
    const int w    = tid >> 5;
    const int r    = lane >> 2;      // 0..7
    const int j    = lane & 3;       // 0..3
    const int rb   = w * 16;         // warp row base within tile

    const int qt = (gridDim.x - 1) - blockIdx.x;   // heavy tiles first
    const int bh = blockIdx.y;
    const int b  = bh >> 4;
    const int h  = bh & 15;
    const float cpen = __ldg(cpen_p);

    const float* Qg = g_Q + (size_t)bh * S_ * DK_;
    const float* Kg = g_K + (size_t)bh * S_ * DK_;
    const float* Vg = g_V + (size_t)bh * S_ * DK_;

    // ---- stage Q tile (64x64) as tf32 ----
    {
        const int row  = tid >> 1;
        const int dh   = (tid & 1) * 32;
        const float* src = Qg + (size_t)(qt * 64 + row) * DK_ + dh;
#pragma unroll
        for (int q = 0; q < 8; ++q)
            *(uint4*)&Qs[row * AP + dh + q * 4] = f2tf4(*(const float4*)(src + q * 4));
    }
    __syncthreads();

    // accumulators: ctx 16x64 per warp -> 8 n-tiles x 4 regs
    float o[8][4];
    float m_lo = -1e30f, m_hi = -1e30f, l_lo = 0.0f, l_hi = 0.0f;
#pragma unroll
    for (int nt = 0; nt < 8; ++nt)
#pragma unroll
        for (int c = 0; c < 4; ++c) o[nt][c] = 0.0f;

    const int nkt = qt + 1;
    for (int kt = 0; kt < nkt; ++kt) {
        __syncthreads();   // previous iter done with Ks/Vt

        // ---- stage K (row-major) and V (transposed) as tf32 ----
        {
            const int row = tid >> 1;
            const int dh  = (tid & 1) * 32;
            const float* ks = Kg + (size_t)(kt * 64 + row) * DK_ + dh;
            const float* vs = Vg + (size_t)(kt * 64 + row) * DK_ + dh;
#pragma unroll
            for (int q = 0; q < 8; ++q) {
                *(uint4*)&Ks[row * AP + dh + q * 4] = f2tf4(*(const float4*)(ks + q * 4));
                float4 vv = *(const float4*)(vs + q * 4);
                const int d0 = dh + q * 4;
                Vt[(d0 + 0) * AP + row] = f2tf(vv.x);
                Vt[(d0 + 1) * AP + row] = f2tf(vv.y);
                Vt[(d0 + 2) * AP + row] = f2tf(vv.z);
                Vt[(d0 + 3) * AP + row] = f2tf(vv.w);
            }
        }
        __syncthreads();

        // ---- S = Q K^T  (warp: 16 rows x 64 keys) ----
        float s[8][4];
#pragma unroll
        for (int nt = 0; nt < 8; ++nt)
#pragma unroll
            for (int c = 0; c < 4; ++c) s[nt][c] = 0.0f;

#pragma unroll
        for (int ks = 0; ks < 8; ++ks) {
            const int k = ks * 8 + j;
            uint32_t a0 = Qs[(rb + r) * AP + k];
            uint32_t a1 = Qs[(rb + r + 8) * AP + k];
            uint32_t a2 = Qs[(rb + r) * AP + k + 4];
            uint32_t a3 = Qs[(rb + r + 8) * AP + k + 4];
#pragma unroll
            for (int nt = 0; nt < 8; ++nt) {
                uint32_t b0 = Ks[(nt * 8 + r) * AP + k];
                uint32_t b1 = Ks[(nt * 8 + r) * AP + k + 4];
                mma_tf32(s[nt][0], s[nt][1], s[nt][2], s[nt][3], a0, a1, a2, a3, b0, b1);
            }
        }

        // ---- scale + penalty + causal mask ----
        const int rowg_lo = qt * 64 + rb + r;
        const int rowg_hi = rowg_lo + 8;
#pragma unroll
        for (int nt = 0; nt < 8; ++nt) {
            const int colg = kt * 64 + nt * 8 + 2 * j;
            const float2 cv = *(const float2*)&cplx[b * S_ + colg];
            const float p0 = cpen * cv.x, p1 = cpen * cv.y;
            s[nt][0] = s[nt][0] * 0.125f - p0;
            s[nt][1] = s[nt][1] * 0.125f - p1;
            s[nt][2] = s[nt][2] * 0.125f - p0;
            s[nt][3] = s[nt][3] * 0.125f - p1;
            if (kt == qt) {
                if (colg     > rowg_lo) s[nt][0] = -1e9f;
                if (colg + 1 > rowg_lo) s[nt][1] = -1e9f;
                if (colg     > rowg_hi) s[nt][2] = -1e9f;
                if (colg + 1 > rowg_hi) s[nt][3] = -1e9f;
            }
        }

        // ---- online softmax (rows lo = c0/c1, hi = c2/c3) ----
        float mx_lo = -1e30f, mx_hi = -1e30f;
#pragma unroll
        for (int nt = 0; nt < 8; ++nt) {
            mx_lo = fmaxf(mx_lo, fmaxf(s[nt][0], s[nt][1]));
            mx_hi = fmaxf(mx_hi, fmaxf(s[nt][2], s[nt][3]));
        }
        mx_lo = fmaxf(mx_lo, __shfl_xor_sync(0xffffffffu, mx_lo, 1));
        mx_lo = fmaxf(mx_lo, __shfl_xor_sync(0xffffffffu, mx_lo, 2));
        mx_hi = fmaxf(mx_hi, __shfl_xor_sync(0xffffffffu, mx_hi, 1));
        mx_hi = fmaxf(mx_hi, __shfl_xor_sync(0xffffffffu, mx_hi, 2));

        const float nm_lo = fmaxf(m_lo, mx_lo);
        const float nm_hi = fmaxf(m_hi, mx_hi);
        const float al_lo = __expf(m_lo - nm_lo);
        const float al_hi = __expf(m_hi - nm_hi);
        m_lo = nm_lo; m_hi = nm_hi;

        float sum_lo = 0.0f, sum_hi = 0.0f;
#pragma unroll
        for (int nt = 0; nt < 8; ++nt) {
            s[nt][0] = __expf(s[nt][0] - nm_lo);
            s[nt][1] = __expf(s[nt][1] - nm_lo);
            s[nt][2] = __expf(s[nt][2] - nm_hi);
            s[nt][3] = __expf(s[nt][3] - nm_hi);
            sum_lo += s[nt][0] + s[nt][1];
            sum_hi += s[nt][2] + s[nt][3];
            // stage P (tf32) into warp-private smem rows
            uint2 plo = make_uint2(f2tf(s[nt][0]), f2tf(s[nt][1]));
            uint2 phi = make_uint2(f2tf(s[nt][2]), f2tf(s[nt][3]));
            *(uint2*)&Ps[(rb + r) * AP + nt * 8 + 2 * j]     = plo;
            *(uint2*)&Ps[(rb + r + 8) * AP + nt * 8 + 2 * j] = phi;
        }
        sum_lo += __shfl_xor_sync(0xffffffffu, sum_lo, 1);
        sum_lo += __shfl_xor_sync(0xffffffffu, sum_lo, 2);
        sum_hi += __shfl_xor_sync(0xffffffffu, sum_hi, 1);
        sum_hi += __shfl_xor_sync(0xffffffffu, sum_hi, 2);
        l_lo = l_lo * al_lo + sum_lo;
        l_hi = l_hi * al_hi + sum_hi;

#pragma unroll
        for (int nt = 0; nt < 8; ++nt) {
            o[nt][0] *= al_lo; o[nt][1] *= al_lo;
            o[nt][2] *= al_hi; o[nt][3] *= al_hi;
        }
        __syncwarp();   // P visible within warp

        // ---- O += P V  (16 rows x 64 d; k-dim = 64 keys) ----
#pragma unroll
        for (int ks = 0; ks < 8; ++ks) {
            const int k = ks * 8 + j;
            uint32_t a0 = Ps[(rb + r) * AP + k];
            uint32_t a1 = Ps[(rb + r + 8) * AP + k];
            uint32_t a2 = Ps[(rb + r) * AP + k + 4];
            uint32_t a3 = Ps[(rb + r + 8) * AP + k + 4];
#pragma unroll
            for (int nt = 0; nt < 8; ++nt) {
                uint32_t b0 = Vt[(nt * 8 + r) * AP + k];
                uint32_t b1 = Vt[(nt * 8 + r) * AP + k + 4];
                mma_tf32(o[nt][0], o[nt][1], o[nt][2], o[nt][3], a0, a1, a2, a3, b0, b1);
            }
        }
        __syncwarp();   // done reading Ps before next iter overwrites
    }

    // ---- epilogue ----
    const float inv_lo = 1.0f / l_lo;
    const float inv_hi = 1.0f / l_hi;
    const int row_lo = qt * 64 + rb + r;
    const int row_hi = row_lo + 8;
#pragma unroll
    for (int nt = 0; nt < 8; ++nt) {
        const int gc = h * DK_ + nt * 8 + 2 * j;
        *(float2*)&g_ctx[(size_t)(b * S_ + row_lo) * D_ + gc] =
            make_float2(o[nt][0] * inv_lo, o[nt][1] * inv_lo);
        *(float2*)&g_ctx[(size_t)(b * S_ + row_hi) * D_ + gc] =
            make_float2(o[nt][2] * inv_hi, o[nt][3] * inv_hi);
    }
}

// ---------------------------------------------------------------------------
// LayerNorm over D=1024 with residual add: out = LN(g_proj + query)*g + b
// ---------------------------------------------------------------------------
__global__ __launch_bounds__(256)
void ln_resid(const float* __restrict__ resid, const float* __restrict__ gamma,
              const float* __restrict__ beta, float* __restrict__ out)
{
    __shared__ float rs[8], rq[8];
    const int row = blockIdx.x;
    const int tid = threadIdx.x;

    const float* xr = g_proj + (size_t)row * D_;
    const float* rr = resid  + (size_t)row * D_;

    float4 a = *(const float4*)&xr[tid * 4];
    float4 r = *(const float4*)&rr[tid * 4];
    float x0 = a.x + r.x, x1 = a.y + r.y, x2 = a.z + r.z, x3 = a.w + r.w;

    float s  = x0 + x1 + x2 + x3;
    float sq = x0 * x0 + x1 * x1 + x2 * x2 + x3 * x3;
#pragma unroll
    for (int off = 16; off >= 1; off >>= 1) {
        s  += __shfl_xor_sync(0xffffffffu, s,  off);
        sq += __shfl_xor_sync(0xffffffffu, sq, off);
    }
    const int wid = tid >> 5;
    if ((tid & 31) == 0) { rs[wid] = s; rq[wid] = sq; }
    __syncthreads();
    float tot = 0.0f, totq = 0.0f;
#pragma unroll
    for (int ww = 0; ww < 8; ++ww) { tot += rs[ww]; totq += rq[ww]; }

    const float mean = tot * (1.0f / D_);
    const float var  = totq * (1.0f / D_) - mean * mean;
    const float rstd = rsqrtf(var + 1e-5f);

    float4 g = *(const float4*)&gamma[tid * 4];
    float4 be = *(const float4*)&beta[tid * 4];
    float4 oo;
    oo.x = (x0 - mean) * rstd * g.x + be.x;
    oo.y = (x1 - mean) * rstd * g.y + be.y;
    oo.z = (x2 - mean) * rstd * g.z + be.z;
    oo.w = (x3 - mean) * rstd * g.w + be.w;
    *(float4*)&out[(size_t)row * D_ + tid * 4] = oo;
}

// ---------------------------------------------------------------------------
// kernel_launch
// ---------------------------------------------------------------------------
extern "C" void kernel_launch(void* const* d_in, const int* in_sizes, int n_in,
                              void* d_out, int out_size)
{
    (void)in_sizes; (void)n_in; (void)out_size;

    const float* query = (const float*)d_in[0];
    const float* key   = (const float*)d_in[1];
    const float* value = (const float*)d_in[2];
    const float* cplx  = (const float*)d_in[3];
    // d_in[4] = mask (bool tril) — deterministic, applied analytically
    const float* wq = (const float*)d_in[5];
    const float* bq = (const float*)d_in[6];
    const float* wk = (const float*)d_in[7];
    const float* bk = (const float*)d_in[8];
    const float* wv = (const float*)d_in[9];
    const float* bv = (const float*)d_in[10];
    const float* wo = (const float*)d_in[11];
    const float* bo = (const float*)d_in[12];
    const float* lng = (const float*)d_in[13];
    const float* lnb = (const float*)d_in[14];
    const float* cpen = (const float*)d_in[15];
    float* out = (float*)d_out;

    void *pQ, *pK, *pV, *pCtx, *pProj;
    cudaGetSymbolAddress(&pQ,   g_Q);
    cudaGetSymbolAddress(&pK,   g_K);
    cudaGetSymbolAddress(&pV,   g_V);
    cudaGetSymbolAddress(&pCtx, g_ctx);
    cudaGetSymbolAddress(&pProj, g_proj);

    const int ATTN_SMEM = 4 * 64 * AP * 4;   // 69632 bytes
    cudaFuncSetAttribute(attn_tc, cudaFuncAttributeMaxDynamicSharedMemorySize,
                         ATTN_SMEM);

    dim3 gg(D_ / 128, BS_ / 128);   // (8, 32)

    // Q/K/V projections -> [B,H,S,DK]
    gemm_tc<1><<<gg, 256>>>(query, wq, bq, (float*)pQ);
    gemm_tc<1><<<gg, 256>>>(key,   wk, bk, (float*)pK);
    gemm_tc<1><<<gg, 256>>>(value, wv, bv, (float*)pV);

    // Flash attention -> g_ctx [B,S,D]
    dim3 ga(S_ / 64, B_ * H_);      // (32, 32)
    attn_tc<<<ga, 128, ATTN_SMEM>>>(cplx, cpen);

    // Output projection -> g_proj [B,S,D]
    gemm_tc<0><<<gg, 256>>>((const float*)pCtx, wo, bo, (float*)pProj);

    // Residual + LayerNorm -> d_out
    ln_resid<<<BS_, 256>>>(query, lng, lnb, out);
}

// round 11
// speedup vs baseline: 1.8031x; 1.1237x over previous
#include <cuda_runtime.h>
#include <math.h>
#include <stdint.h>

// Problem constants
#define B_   2
#define S_   2048
#define D_   1024
#define H_   16
#define DK_  64
#define BS_  (B_ * S_)   // 4096

// ---------------------------------------------------------------------------
// Device scratch (no allocations allowed -> __device__ globals)
// ---------------------------------------------------------------------------
__device__ float g_Q[B_ * H_ * S_ * DK_];     // [B,H,S,DK]  (tf32-rounded)
__device__ float g_K[B_ * H_ * S_ * DK_];
__device__ float g_V[B_ * H_ * S_ * DK_];
__device__ float g_ctx[B_ * S_ * D_];         // [B,S,D]     (tf32-rounded)
__device__ float g_proj[B_ * S_ * D_];        // out-proj result (exact fp32)
__device__ float g_rW[4 * D_ * D_];           // rounded wq,wk,wv,wo
__device__ float g_rX[3 * BS_ * D_];          // rounded query,key,value

// ---------------------------------------------------------------------------
// tf32 + cp.async helpers
// ---------------------------------------------------------------------------
__device__ __forceinline__ uint32_t f2tf(float f) {
    uint32_t u;
    asm("cvt.rna.tf32.f32 %0, %1;" : "=r"(u) : "f"(f));
    return u;
}
__device__ __forceinline__ uint4 f2tf4(float4 v) {
    uint4 u;
    u.x = f2tf(v.x); u.y = f2tf(v.y); u.z = f2tf(v.z); u.w = f2tf(v.w);
    return u;
}
__device__ __forceinline__ void cp16(uint32_t dst, const void* src) {
    asm volatile("cp.async.cg.shared.global [%0], [%1], 16;\n"
                 :: "r"(dst), "l"(src));
}
__device__ __forceinline__ void cp_commit() {
    asm volatile("cp.async.commit_group;\n");
}
template <int N>
__device__ __forceinline__ void cp_wait() {
    asm volatile("cp.async.wait_group %0;\n" :: "n"(N));
}
// D(16x8,f32) += A(16x8,tf32,row) * B(8x8,tf32,col)
__device__ __forceinline__ void mma_tf32(float& d0, float& d1, float& d2, float& d3,
                                         uint32_t a0, uint32_t a1, uint32_t a2, uint32_t a3,
                                         uint32_t b0, uint32_t b1) {
    asm volatile(
        "mma.sync.aligned.m16n8k8.row.col.f32.tf32.tf32.f32 "
        "{%0,%1,%2,%3}, {%4,%5,%6,%7}, {%8,%9}, {%0,%1,%2,%3};\n"
        : "+f"(d0), "+f"(d1), "+f"(d2), "+f"(d3)
        : "r"(a0), "r"(a1), "r"(a2), "r"(a3), "r"(b0), "r"(b1));
}

// ---------------------------------------------------------------------------
// Elementwise tf32 rounding pass (src -> dst), n multiple of 4
// ---------------------------------------------------------------------------
__global__ void round_pass(const float* __restrict__ src, float* __restrict__ dst,
                           int n)
{
    const int i = (blockIdx.x * blockDim.x + threadIdx.x) * 4;
    if (i < n) {
        uint4 u = f2tf4(*(const float4*)(src + i));
        *(float4*)(dst + i) = make_float4(__uint_as_float(u.x), __uint_as_float(u.y),
                                          __uint_as_float(u.z), __uint_as_float(u.w));
    }
}

// ---------------------------------------------------------------------------
// tf32 tensor-core GEMM: Y[m][n] = sum_k A[m][k]*W[n][k] + bias[n]
//   A, W already tf32-rounded fp32. MODE 0: row-major out (exact fp32);
//   MODE 1: out scattered to [B,H,S,DK], tf32-rounded.
// CTA 128x128, 256 thr, warp tile 64x32. k16 chunks, 3-stage cp.async
// pipeline, smem pitch 20 (conflict-free fragment gathers), 1 barrier/chunk.
// ---------------------------------------------------------------------------
#define GP 20

template <int MODE>
__global__ __launch_bounds__(256, 2)
void gemm_tc(const float* __restrict__ A, const float* __restrict__ W,
             const float* __restrict__ bias, float* __restrict__ out)
{
    __shared__ uint32_t As[3][128 * GP];
    __shared__ uint32_t Bs[3][128 * GP];

    const int tid  = threadIdx.x;
    const int lane = tid & 31;
    const int w    = tid >> 5;
    const int wm   = w & 1;
    const int wn   = w >> 1;
    const int row0 = blockIdx.y * 128;
    const int col0 = blockIdx.x * 128;
    const int r = lane >> 2;
    const int j = lane & 3;

    const int lrow = tid & 127;
    const int lkq  = (tid >> 7) << 3;   // 0 or 8

    const float* Aptr = A + (size_t)(row0 + lrow) * D_ + lkq;
    const float* Wptr = W + (size_t)(col0 + lrow) * D_ + lkq;

    uint32_t sA[3], sB[3];
#pragma unroll
    for (int s = 0; s < 3; ++s) {
        sA[s] = (uint32_t)__cvta_generic_to_shared(&As[s][lrow * GP + lkq]);
        sB[s] = (uint32_t)__cvta_generic_to_shared(&Bs[s][lrow * GP + lkq]);
    }

    float acc[4][4][4];
#pragma unroll
    for (int mt = 0; mt < 4; ++mt)
#pragma unroll
        for (int nt = 0; nt < 4; ++nt)
#pragma unroll
            for (int c = 0; c < 4; ++c) acc[mt][nt][c] = 0.0f;

    // prologue: stage chunks 0,1
#pragma unroll
    for (int t = 0; t < 2; ++t) {
        cp16(sA[t],      Aptr + t * 16);
        cp16(sA[t] + 16, Aptr + t * 16 + 4);
        cp16(sB[t],      Wptr + t * 16);
        cp16(sB[t] + 16, Wptr + t * 16 + 4);
        cp_commit();
    }

    const int arow = (wm * 64 + r) * GP;
    const int brow = (wn * 32 + r) * GP;

    constexpr int TILES = D_ / 16;   // 64
    for (int t = 0; t < TILES; ++t) {
        if (t < TILES - 1) cp_wait<1>(); else cp_wait<0>();
        __syncthreads();

        if (t + 2 < TILES) {
            const int nb = (t + 2) % 3;
            const float* a  = Aptr + (t + 2) * 16;
            const float* wv = Wptr + (t + 2) * 16;
            cp16(sA[nb],      a);
            cp16(sA[nb] + 16, a + 4);
            cp16(sB[nb],      wv);
            cp16(sB[nb] + 16, wv + 4);
            cp_commit();
        }

        const uint32_t* Ab = As[t % 3];
        const uint32_t* Bb = Bs[t % 3];
#pragma unroll
        for (int ss = 0; ss < 2; ++ss) {
            const int k = ss * 8 + j;
            uint32_t af[4][4];
#pragma unroll
            for (int mt = 0; mt < 4; ++mt) {
                const int base = arow + mt * 16 * GP;
                af[mt][0] = Ab[base + k];
                af[mt][1] = Ab[base + 8 * GP + k];
                af[mt][2] = Ab[base + k + 4];
                af[mt][3] = Ab[base + 8 * GP + k + 4];
            }
#pragma unroll
            for (int nt = 0; nt < 4; ++nt) {
                const int base = brow + nt * 8 * GP;
                uint32_t b0 = Bb[base + k];
                uint32_t b1 = Bb[base + k + 4];
#pragma unroll
                for (int mt = 0; mt < 4; ++mt)
                    mma_tf32(acc[mt][nt][0], acc[mt][nt][1], acc[mt][nt][2], acc[mt][nt][3],
                             af[mt][0], af[mt][1], af[mt][2], af[mt][3], b0, b1);
            }
        }
        __syncthreads();
    }

    // epilogue
#pragma unroll
    for (int mt = 0; mt < 4; ++mt) {
        const int gr = row0 + wm * 64 + mt * 16 + r;
#pragma unroll
        for (int nt = 0; nt < 4; ++nt) {
            const int gc = col0 + wn * 32 + nt * 8 + 2 * j;
            const float2 bb = *(const float2*)&bias[gc];
            float2 v0 = make_float2(acc[mt][nt][0] + bb.x, acc[mt][nt][1] + bb.y);
            float2 v1 = make_float2(acc[mt][nt][2] + bb.x, acc[mt][nt][3] + bb.y);
            if (MODE == 0) {
                *(float2*)&out[(size_t)gr * D_ + gc]       = v0;
                *(float2*)&out[(size_t)(gr + 8) * D_ + gc] = v1;
            } else {
                // round to tf32 (consumed by attention MMAs)
                v0 = make_float2(__uint_as_float(f2tf(v0.x)), __uint_as_float(f2tf(v0.y)));
                v1 = make_float2(__uint_as_float(f2tf(v1.x)), __uint_as_float(f2tf(v1.y)));
                const int h  = gc >> 6;
                const int dk = gc & 63;
                const int b0i = gr >> 11, s0 = gr & (S_ - 1);
                const int gr1 = gr + 8;
                const int b1i = gr1 >> 11, s1 = gr1 & (S_ - 1);
                *(float2*)&out[(((size_t)(b0i * H_ + h) * S_) + s0) * DK_ + dk] = v0;
                *(float2*)&out[(((size_t)(b1i * H_ + h) * S_) + s1) * DK_ + dk] = v1;
            }
        }
    }
}

// ---------------------------------------------------------------------------
// Flash attention, tf32 tensor cores, cp.async double-buffered K/V.
// CTA 128 thr (4 warps), Q tile 64 rows, K tile 64 keys; warp = one m16 slice.
// smem (dynamic, 104 KB): Qs[64][68], Ks[2][64][68], Vs[2][64][72] (row-major!),
// Ps[64][68]. Pitches: 68 = 4 (mod 32), 72 = 8 (mod 32) -> conflict-free frags.
// One __syncthreads per k-tile; K/V fetch overlaps the MMA work.
// ---------------------------------------------------------------------------
#define AP 68
#define VP 72

__global__ __launch_bounds__(128)
void attn_tc(const float* __restrict__ cplx, const float* __restrict__ cpen_p)
{
    extern __shared__ uint32_t smem[];
    uint32_t* Qs  = smem;                 // 64*AP
    uint32_t* Ks0 = Qs  + 64 * AP;
    uint32_t* Ks1 = Ks0 + 64 * AP;
    uint32_t* Vs0 = Ks1 + 64 * AP;
    uint32_t* Vs1 = Vs0 + 64 * VP;
    uint32_t* Ps  = Vs1 + 64 * VP;        // 64*AP

    const int tid  = threadIdx.x;
    const int lane = tid & 31;
    const int w    = tid >> 5;
    const int r    = lane >> 2;
    const int j    = lane & 3;
    const int rb   = w * 16;

    const int qt = (gridDim.x - 1) - blockIdx.x;   // heavy tiles first
    const int bh = blockIdx.y;
    const int b  = bh >> 4;
    const int h  = bh & 15;
    const float cpen = __ldg(cpen_p);

    const float* Qg = g_Q + (size_t)bh * S_ * DK_;
    const float* Kg = g_K + (size_t)bh * S_ * DK_;
    const float* Vg = g_V + (size_t)bh * S_ * DK_;

    // staging mapping: thread -> (row, 32-float half)
    const int srow  = tid >> 1;
    const int shalf = (tid & 1) * 32;
    const uint32_t qdst = (uint32_t)__cvta_generic_to_shared(&Qs[srow * AP + shalf]);
    uint32_t kdst[2] = {
        (uint32_t)__cvta_generic_to_shared(&Ks0[srow * AP + shalf]),
        (uint32_t)__cvta_generic_to_shared(&Ks1[srow * AP + shalf]) };
    uint32_t vdst[2] = {
        (uint32_t)__cvta_generic_to_shared(&Vs0[srow * VP + shalf]),
        (uint32_t)__cvta_generic_to_shared(&Vs1[srow * VP + shalf]) };

    auto stage_kv = [&](int kt, int buf) {
        const float* ks = Kg + (size_t)(kt * 64 + srow) * DK_ + shalf;
        const float* vs = Vg + (size_t)(kt * 64 + srow) * DK_ + shalf;
#pragma unroll
        for (int q = 0; q < 8; ++q) {
            cp16(kdst[buf] + q * 16, ks + q * 4);
            cp16(vdst[buf] + q * 16, vs + q * 4);
        }
    };

    // prologue: Q + first K/V tile in group 0
    {
        const float* qs = Qg + (size_t)(qt * 64 + srow) * DK_ + shalf;
#pragma unroll
        for (int q = 0; q < 8; ++q) cp16(qdst + q * 16, qs + q * 4);
        stage_kv(0, 0);
        cp_commit();
    }

    float o[8][4];
    float m_lo = -1e30f, m_hi = -1e30f, l_lo = 0.0f, l_hi = 0.0f;
#pragma unroll
    for (int nt = 0; nt < 8; ++nt)
#pragma unroll
        for (int c = 0; c < 4; ++c) o[nt][c] = 0.0f;

    const int nkt = qt + 1;
    for (int kt = 0; kt < nkt; ++kt) {
        cp_wait<0>();
        __syncthreads();   // staged data visible; prior compute done everywhere

        if (kt + 1 < nkt) { stage_kv(kt + 1, (kt + 1) & 1); cp_commit(); }

        const uint32_t* Kb = (kt & 1) ? Ks1 : Ks0;
        const uint32_t* Vb = (kt & 1) ? Vs1 : Vs0;

        // ---- S = Q K^T  (warp: 16 rows x 64 keys) ----
        float s[8][4];
#pragma unroll
        for (int nt = 0; nt < 8; ++nt)
#pragma unroll
            for (int c = 0; c < 4; ++c) s[nt][c] = 0.0f;

#pragma unroll
        for (int ks = 0; ks < 8; ++ks) {
            const int k = ks * 8 + j;
            uint32_t a0 = Qs[(rb + r) * AP + k];
            uint32_t a1 = Qs[(rb + r + 8) * AP + k];
            uint32_t a2 = Qs[(rb + r) * AP + k + 4];
            uint32_t a3 = Qs[(rb + r + 8) * AP + k + 4];
#pragma unroll
            for (int nt = 0; nt < 8; ++nt) {
                uint32_t b0 = Kb[(nt * 8 + r) * AP + k];
                uint32_t b1 = Kb[(nt * 8 + r) * AP + k + 4];
                mma_tf32(s[nt][0], s[nt][1], s[nt][2], s[nt][3], a0, a1, a2, a3, b0, b1);
            }
        }

        // ---- scale + penalty + causal mask ----
        const int rowg_lo = qt * 64 + rb + r;
        const int rowg_hi = rowg_lo + 8;
#pragma unroll
        for (int nt = 0; nt < 8; ++nt) {
            const int colg = kt * 64 + nt * 8 + 2 * j;
            const float2 cv = *(const float2*)&cplx[b * S_ + colg];
            const float p0 = cpen * cv.x, p1 = cpen * cv.y;
            s[nt][0] = s[nt][0] * 0.125f - p0;
            s[nt][1] = s[nt][1] * 0.125f - p1;
            s[nt][2] = s[nt][2] * 0.125f - p0;
            s[nt][3] = s[nt][3] * 0.125f - p1;
            if (kt == qt) {
                if (colg     > rowg_lo) s[nt][0] = -1e9f;
                if (colg + 1 > rowg_lo) s[nt][1] = -1e9f;
                if (colg     > rowg_hi) s[nt][2] = -1e9f;
                if (colg + 1 > rowg_hi) s[nt][3] = -1e9f;
            }
        }

        // ---- online softmax ----
        float mx_lo = -1e30f, mx_hi = -1e30f;
#pragma unroll
        for (int nt = 0; nt < 8; ++nt) {
            mx_lo = fmaxf(mx_lo, fmaxf(s[nt][0], s[nt][1]));
            mx_hi = fmaxf(mx_hi, fmaxf(s[nt][2], s[nt][3]));
        }
        mx_lo = fmaxf(mx_lo, __shfl_xor_sync(0xffffffffu, mx_lo, 1));
        mx_lo = fmaxf(mx_lo, __shfl_xor_sync(0xffffffffu, mx_lo, 2));
        mx_hi = fmaxf(mx_hi, __shfl_xor_sync(0xffffffffu, mx_hi, 1));
        mx_hi = fmaxf(mx_hi, __shfl_xor_sync(0xffffffffu, mx_hi, 2));

        const float nm_lo = fmaxf(m_lo, mx_lo);
        const float nm_hi = fmaxf(m_hi, mx_hi);
        const float al_lo = __expf(m_lo - nm_lo);
        const float al_hi = __expf(m_hi - nm_hi);
        m_lo = nm_lo; m_hi = nm_hi;

        float sum_lo = 0.0f, sum_hi = 0.0f;
#pragma unroll
        for (int nt = 0; nt < 8; ++nt) {
            s[nt][0] = __expf(s[nt][0] - nm_lo);
            s[nt][1] = __expf(s[nt][1] - nm_lo);
            s[nt][2] = __expf(s[nt][2] - nm_hi);
            s[nt][3] = __expf(s[nt][3] - nm_hi);
            sum_lo += s[nt][0] + s[nt][1];
            sum_hi += s[nt][2] + s[nt][3];
            uint2 plo = make_uint2(f2tf(s[nt][0]), f2tf(s[nt][1]));
            uint2 phi = make_uint2(f2tf(s[nt][2]), f2tf(s[nt][3]));
            *(uint2*)&Ps[(rb + r) * AP + nt * 8 + 2 * j]     = plo;
            *(uint2*)&Ps[(rb + r + 8) * AP + nt * 8 + 2 * j] = phi;
        }
        sum_lo += __shfl_xor_sync(0xffffffffu, sum_lo, 1);
        sum_lo += __shfl_xor_sync(0xffffffffu, sum_lo, 2);
        sum_hi += __shfl_xor_sync(0xffffffffu, sum_hi, 1);
        sum_hi += __shfl_xor_sync(0xffffffffu, sum_hi, 2);
        l_lo = l_lo * al_lo + sum_lo;
        l_hi = l_hi * al_hi + sum_hi;

#pragma unroll
        for (int nt = 0; nt < 8; ++nt) {
            o[nt][0] *= al_lo; o[nt][1] *= al_lo;
            o[nt][2] *= al_hi; o[nt][3] *= al_hi;
        }
        __syncwarp();   // P visible within warp

        // ---- O += P V  (V row-major: B[k=key][n=d], pitch 72) ----
#pragma unroll
        for (int ks = 0; ks < 8; ++ks) {
            const int k = ks * 8 + j;
            uint32_t a0 = Ps[(rb + r) * AP + k];
            uint32_t a1 = Ps[(rb + r + 8) * AP + k];
            uint32_t a2 = Ps[(rb + r) * AP + k + 4];
            uint32_t a3 = Ps[(rb + r + 8) * AP + k + 4];
            const int krow0 = (ks * 8 + j) * VP;
            const int krow1 = (ks * 8 + j + 4) * VP;
#pragma unroll
            for (int nt = 0; nt < 8; ++nt) {
                uint32_t b0 = Vb[krow0 + nt * 8 + r];
                uint32_t b1 = Vb[krow1 + nt * 8 + r];
                mma_tf32(o[nt][0], o[nt][1], o[nt][2], o[nt][3], a0, a1, a2, a3, b0, b1);
            }
        }
    }

    // ---- epilogue (ctx written tf32-rounded for the Wo GEMM) ----
    const float inv_lo = 1.0f / l_lo;
    const float inv_hi = 1.0f / l_hi;
    const int row_lo = qt * 64 + rb + r;
    const int row_hi = row_lo + 8;
#pragma unroll
    for (int nt = 0; nt < 8; ++nt) {
        const int gc = h * DK_ + nt * 8 + 2 * j;
        *(float2*)&g_ctx[(size_t)(b * S_ + row_lo) * D_ + gc] =
            make_float2(__uint_as_float(f2tf(o[nt][0] * inv_lo)),
                        __uint_as_float(f2tf(o[nt][1] * inv_lo)));
        *(float2*)&g_ctx[(size_t)(b * S_ + row_hi) * D_ + gc] =
            make_float2(__uint_as_float(f2tf(o[nt][2] * inv_hi)),
                        __uint_as_float(f2tf(o[nt][3] * inv_hi)));
    }
}

// ---------------------------------------------------------------------------
// LayerNorm over D=1024 with residual add: out = LN(g_proj + query)*g + b
// ---------------------------------------------------------------------------
__global__ __launch_bounds__(256)
void ln_resid(const float* __restrict__ resid, const float* __restrict__ gamma,
              const float* __restrict__ beta, float* __restrict__ out)
{
    __shared__ float rs[8], rq[8];
    const int row = blockIdx.x;
    const int tid = threadIdx.x;

    const float* xr = g_proj + (size_t)row * D_;
    const float* rr = resid  + (size_t)row * D_;

    float4 a = *(const float4*)&xr[tid * 4];
    float4 r = *(const float4*)&rr[tid * 4];
    float x0 = a.x + r.x, x1 = a.y + r.y, x2 = a.z + r.z, x3 = a.w + r.w;

    float s  = x0 + x1 + x2 + x3;
    float sq = x0 * x0 + x1 * x1 + x2 * x2 + x3 * x3;
#pragma unroll
    for (int off = 16; off >= 1; off >>= 1) {
        s  += __shfl_xor_sync(0xffffffffu, s,  off);
        sq += __shfl_xor_sync(0xffffffffu, sq, off);
    }
    const int wid = tid >> 5;
    if ((tid & 31) == 0) { rs[wid] = s; rq[wid] = sq; }
    __syncthreads();
    float tot = 0.0f, totq = 0.0f;
#pragma unroll
    for (int ww = 0; ww < 8; ++ww) { tot += rs[ww]; totq += rq[ww]; }

    const float mean = tot * (1.0f / D_);
    const float var  = totq * (1.0f / D_) - mean * mean;
    const float rstd = rsqrtf(var + 1e-5f);

    float4 g = *(const float4*)&gamma[tid * 4];
    float4 be = *(const float4*)&beta[tid * 4];
    float4 oo;
    oo.x = (x0 - mean) * rstd * g.x + be.x;
    oo.y = (x1 - mean) * rstd * g.y + be.y;
    oo.z = (x2 - mean) * rstd * g.z + be.z;
    oo.w = (x3 - mean) * rstd * g.w + be.w;
    *(float4*)&out[(size_t)row * D_ + tid * 4] = oo;
}

// ---------------------------------------------------------------------------
// kernel_launch
// ---------------------------------------------------------------------------
extern "C" void kernel_launch(void* const* d_in, const int* in_sizes, int n_in,
                              void* d_out, int out_size)
{
    (void)in_sizes; (void)n_in; (void)out_size;

    const float* query = (const float*)d_in[0];
    const float* key   = (const float*)d_in[1];
    const float* value = (const float*)d_in[2];
    const float* cplx  = (const float*)d_in[3];
    // d_in[4] = mask (bool tril) — deterministic, applied analytically
    const float* wq = (const float*)d_in[5];
    const float* bq = (const float*)d_in[6];
    const float* wk = (const float*)d_in[7];
    const float* bk = (const float*)d_in[8];
    const float* wv = (const float*)d_in[9];
    const float* bv = (const float*)d_in[10];
    const float* wo = (const float*)d_in[11];
    const float* bo = (const float*)d_in[12];
    const float* lng = (const float*)d_in[13];
    const float* lnb = (const float*)d_in[14];
    const float* cpen = (const float*)d_in[15];
    float* out = (float*)d_out;

    void *pQ, *pK, *pV, *pCtx, *pProj, *pRW, *pRX;
    cudaGetSymbolAddress(&pQ,    g_Q);
    cudaGetSymbolAddress(&pK,    g_K);
    cudaGetSymbolAddress(&pV,    g_V);
    cudaGetSymbolAddress(&pCtx,  g_ctx);
    cudaGetSymbolAddress(&pProj, g_proj);
    cudaGetSymbolAddress(&pRW,   g_rW);
    cudaGetSymbolAddress(&pRX,   g_rX);
    float* rW = (float*)pRW;
    float* rX = (float*)pRX;

    const int ATTN_SMEM = (64 * AP * 2 + 64 * AP * 2 + 64 * VP * 2) * 4; // 106496
    cudaFuncSetAttribute(attn_tc, cudaFuncAttributeMaxDynamicSharedMemorySize,
                         ATTN_SMEM);

    // ---- pre-round weights & activations to tf32 (kills MMA-input bias) ----
    const int NW = D_ * D_;       // 1 M
    const int NX = BS_ * D_;      // 4 M
    round_pass<<<NW / 1024, 256>>>(wq, rW + 0 * (size_t)NW, NW);
    round_pass<<<NW / 1024, 256>>>(wk, rW + 1 * (size_t)NW, NW);
    round_pass<<<NW / 1024, 256>>>(wv, rW + 2 * (size_t)NW, NW);
    round_pass<<<NW / 1024, 256>>>(wo, rW + 3 * (size_t)NW, NW);
    round_pass<<<NX / 1024, 256>>>(query, rX + 0 * (size_t)NX, NX);
    round_pass<<<NX / 1024, 256>>>(key,   rX + 1 * (size_t)NX, NX);
    round_pass<<<NX / 1024, 256>>>(value, rX + 2 * (size_t)NX, NX);

    dim3 gg(D_ / 128, BS_ / 128);   // (8, 32)

    // Q/K/V projections -> [B,H,S,DK] (tf32-rounded outputs)
    gemm_tc<1><<<gg, 256>>>(rX + 0 * (size_t)NX, rW + 0 * (size_t)NW, bq, (float*)pQ);
    gemm_tc<1><<<gg, 256>>>(rX + 1 * (size_t)NX, rW + 1 * (size_t)NW, bk, (float*)pK);
    gemm_tc<1><<<gg, 256>>>(rX + 2 * (size_t)NX, rW + 2 * (size_t)NW, bv, (float*)pV);

    // Flash attention -> g_ctx (tf32-rounded)
    dim3 ga(S_ / 64, B_ * H_);      // (32, 32)
    attn_tc<<<ga, 128, ATTN_SMEM>>>(cplx, cpen);

    // Output projection -> g_proj (exact fp32)
    gemm_tc<0><<<gg, 256>>>((const float*)pCtx, rW + 3 * (size_t)NW, bo, (float*)pProj);

    // Residual + LayerNorm -> d_out
    ln_resid<<<BS_, 256>>>(query, lng, lnb, out);
}

// round 12
// speedup vs baseline: 1.9028x; 1.0553x over previous
#include <cuda_runtime.h>
#include <math.h>
#include <stdint.h>

// Problem constants
#define B_   2
#define S_   2048
#define D_   1024
#define H_   16
#define DK_  64
#define BS_  (B_ * S_)   // 4096

// ---------------------------------------------------------------------------
// Device scratch (no allocations allowed -> __device__ globals)
// ---------------------------------------------------------------------------
__device__ float g_Q[B_ * H_ * S_ * DK_];     // [B,H,S,DK]  (tf32-rounded)
__device__ float g_K[B_ * H_ * S_ * DK_];
__device__ float g_V[B_ * H_ * S_ * DK_];
__device__ float g_ctx[B_ * S_ * D_];         // [B,S,D]     (tf32-rounded)
__device__ float g_proj[B_ * S_ * D_];        // out-proj result (exact fp32)
__device__ float g_rW[4 * D_ * D_];           // rounded wq,wk,wv,wo
__device__ float g_rX[3 * BS_ * D_];          // rounded query,key,value

// ---------------------------------------------------------------------------
// tf32 + cp.async helpers
// ---------------------------------------------------------------------------
__device__ __forceinline__ uint32_t f2tf(float f) {
    uint32_t u;
    asm("cvt.rna.tf32.f32 %0, %1;" : "=r"(u) : "f"(f));
    return u;
}
__device__ __forceinline__ uint4 f2tf4(float4 v) {
    uint4 u;
    u.x = f2tf(v.x); u.y = f2tf(v.y); u.z = f2tf(v.z); u.w = f2tf(v.w);
    return u;
}
__device__ __forceinline__ void cp16(uint32_t dst, const void* src) {
    asm volatile("cp.async.cg.shared.global [%0], [%1], 16;\n"
                 :: "r"(dst), "l"(src));
}
__device__ __forceinline__ void cp_commit() {
    asm volatile("cp.async.commit_group;\n");
}
template <int N>
__device__ __forceinline__ void cp_wait() {
    asm volatile("cp.async.wait_group %0;\n" :: "n"(N));
}
// D(16x8,f32) += A(16x8,tf32,row) * B(8x8,tf32,col)
__device__ __forceinline__ void mma_tf32(float& d0, float& d1, float& d2, float& d3,
                                         uint32_t a0, uint32_t a1, uint32_t a2, uint32_t a3,
                                         uint32_t b0, uint32_t b1) {
    asm volatile(
        "mma.sync.aligned.m16n8k8.row.col.f32.tf32.tf32.f32 "
        "{%0,%1,%2,%3}, {%4,%5,%6,%7}, {%8,%9}, {%0,%1,%2,%3};\n"
        : "+f"(d0), "+f"(d1), "+f"(d2), "+f"(d3)
        : "r"(a0), "r"(a1), "r"(a2), "r"(a3), "r"(b0), "r"(b1));
}

// ---------------------------------------------------------------------------
// Elementwise tf32 rounding pass (src -> dst), n multiple of 4
// ---------------------------------------------------------------------------
__global__ void round_pass(const float* __restrict__ src, float* __restrict__ dst,
                           int n)
{
    const int i = (blockIdx.x * blockDim.x + threadIdx.x) * 4;
    if (i < n) {
        uint4 u = f2tf4(*(const float4*)(src + i));
        *(float4*)(dst + i) = make_float4(__uint_as_float(u.x), __uint_as_float(u.y),
                                          __uint_as_float(u.z), __uint_as_float(u.w));
    }
}

// ---------------------------------------------------------------------------
// tf32 tensor-core GEMM body: Y[m][n] = sum_k A[m][k]*W[n][k] + bias[n]
//   A, W already tf32-rounded fp32. MODE 0: row-major out (exact fp32);
//   MODE 1: out scattered to [B,H,S,DK], tf32-rounded.
// CTA 128x128, 256 thr, warp tile 64x32. k16 chunks, 3-stage cp.async
// pipeline, smem pitch 20 (conflict-free fragment gathers).
// ---------------------------------------------------------------------------
#define GP 20

template <int MODE>
__device__ __forceinline__
void gemm_body(const float* __restrict__ A, const float* __restrict__ W,
               const float* __restrict__ bias, float* __restrict__ out,
               uint32_t (*As)[128 * GP], uint32_t (*Bs)[128 * GP])
{
    const int tid  = threadIdx.x;
    const int lane = tid & 31;
    const int w    = tid >> 5;
    const int wm   = w & 1;
    const int wn   = w >> 1;
    const int row0 = blockIdx.y * 128;
    const int col0 = blockIdx.x * 128;
    const int r = lane >> 2;
    const int j = lane & 3;

    const int lrow = tid & 127;
    const int lkq  = (tid >> 7) << 3;   // 0 or 8

    const float* Aptr = A + (size_t)(row0 + lrow) * D_ + lkq;
    const float* Wptr = W + (size_t)(col0 + lrow) * D_ + lkq;

    uint32_t sA[3], sB[3];
#pragma unroll
    for (int s = 0; s < 3; ++s) {
        sA[s] = (uint32_t)__cvta_generic_to_shared(&As[s][lrow * GP + lkq]);
        sB[s] = (uint32_t)__cvta_generic_to_shared(&Bs[s][lrow * GP + lkq]);
    }

    float acc[4][4][4];
#pragma unroll
    for (int mt = 0; mt < 4; ++mt)
#pragma unroll
        for (int nt = 0; nt < 4; ++nt)
#pragma unroll
            for (int c = 0; c < 4; ++c) acc[mt][nt][c] = 0.0f;

    // prologue: stage chunks 0,1
#pragma unroll
    for (int t = 0; t < 2; ++t) {
        cp16(sA[t],      Aptr + t * 16);
        cp16(sA[t] + 16, Aptr + t * 16 + 4);
        cp16(sB[t],      Wptr + t * 16);
        cp16(sB[t] + 16, Wptr + t * 16 + 4);
        cp_commit();
    }

    const int arow = (wm * 64 + r) * GP;
    const int brow = (wn * 32 + r) * GP;

    constexpr int TILES = D_ / 16;   // 64
    for (int t = 0; t < TILES; ++t) {
        if (t < TILES - 1) cp_wait<1>(); else cp_wait<0>();
        __syncthreads();

        if (t + 2 < TILES) {
            const int nb = (t + 2) % 3;
            const float* a  = Aptr + (t + 2) * 16;
            const float* wv = Wptr + (t + 2) * 16;
            cp16(sA[nb],      a);
            cp16(sA[nb] + 16, a + 4);
            cp16(sB[nb],      wv);
            cp16(sB[nb] + 16, wv + 4);
            cp_commit();
        }

        const uint32_t* Ab = As[t % 3];
        const uint32_t* Bb = Bs[t % 3];
#pragma unroll
        for (int ss = 0; ss < 2; ++ss) {
            const int k = ss * 8 + j;
            uint32_t af[4][4];
#pragma unroll
            for (int mt = 0; mt < 4; ++mt) {
                const int base = arow + mt * 16 * GP;
                af[mt][0] = Ab[base + k];
                af[mt][1] = Ab[base + 8 * GP + k];
                af[mt][2] = Ab[base + k + 4];
                af[mt][3] = Ab[base + 8 * GP + k + 4];
            }
#pragma unroll
            for (int nt = 0; nt < 4; ++nt) {
                const int base = brow + nt * 8 * GP;
                uint32_t b0 = Bb[base + k];
                uint32_t b1 = Bb[base + k + 4];
#pragma unroll
                for (int mt = 0; mt < 4; ++mt)
                    mma_tf32(acc[mt][nt][0], acc[mt][nt][1], acc[mt][nt][2], acc[mt][nt][3],
                             af[mt][0], af[mt][1], af[mt][2], af[mt][3], b0, b1);
            }
        }
        __syncthreads();
    }

    // epilogue
#pragma unroll
    for (int mt = 0; mt < 4; ++mt) {
        const int gr = row0 + wm * 64 + mt * 16 + r;
#pragma unroll
        for (int nt = 0; nt < 4; ++nt) {
            const int gc = col0 + wn * 32 + nt * 8 + 2 * j;
            const float2 bb = *(const float2*)&bias[gc];
            float2 v0 = make_float2(acc[mt][nt][0] + bb.x, acc[mt][nt][1] + bb.y);
            float2 v1 = make_float2(acc[mt][nt][2] + bb.x, acc[mt][nt][3] + bb.y);
            if (MODE == 0) {
                *(float2*)&out[(size_t)gr * D_ + gc]       = v0;
                *(float2*)&out[(size_t)(gr + 8) * D_ + gc] = v1;
            } else {
                // round to tf32 (consumed by attention MMAs)
                v0 = make_float2(__uint_as_float(f2tf(v0.x)), __uint_as_float(f2tf(v0.y)));
                v1 = make_float2(__uint_as_float(f2tf(v1.x)), __uint_as_float(f2tf(v1.y)));
                const int h  = gc >> 6;
                const int dk = gc & 63;
                const int b0i = gr >> 11, s0 = gr & (S_ - 1);
                const int gr1 = gr + 8;
                const int b1i = gr1 >> 11, s1 = gr1 & (S_ - 1);
                *(float2*)&out[(((size_t)(b0i * H_ + h) * S_) + s0) * DK_ + dk] = v0;
                *(float2*)&out[(((size_t)(b1i * H_ + h) * S_) + s1) * DK_ + dk] = v1;
            }
        }
    }
}

// wo projection: single GEMM, row-major fp32 out
__global__ __launch_bounds__(256, 2)
void gemm_tc0(const float* __restrict__ A, const float* __restrict__ W,
              const float* __restrict__ bias, float* __restrict__ out)
{
    __shared__ uint32_t As[3][128 * GP];
    __shared__ uint32_t Bs[3][128 * GP];
    gemm_body<0>(A, W, bias, out, As, Bs);
}

// QKV projections merged: blockIdx.z selects {q,k,v} -> dense wave packing
__global__ __launch_bounds__(256, 2)
void gemm_qkv(const float* __restrict__ X, const float* __restrict__ W4,
              const float* __restrict__ bq, const float* __restrict__ bk,
              const float* __restrict__ bv,
              float* __restrict__ oq, float* __restrict__ ok,
              float* __restrict__ ov)
{
    __shared__ uint32_t As[3][128 * GP];
    __shared__ uint32_t Bs[3][128 * GP];
    const int z = blockIdx.z;
    const size_t NX = (size_t)BS_ * D_;
    const size_t NW = (size_t)D_ * D_;
    const float* A    = X  + z * NX;
    const float* W    = W4 + z * NW;
    const float* bias = (z == 0) ? bq : (z == 1) ? bk : bv;
    float*       out  = (z == 0) ? oq : (z == 1) ? ok : ov;
    gemm_body<1>(A, W, bias, out, As, Bs);
}

// ---------------------------------------------------------------------------
// Flash attention, tf32 tensor cores, cp.async double-buffered K/V.
// CTA 256 thr (8 warps), Q tile 128 rows, K tile 64 keys; warp = one m16 slice.
// smem (dynamic, 138 KB): Qs[128][68], Ks[2][64][68], Vs[2][64][72] (row-major),
// Ps[128][68]. Pitches 68 = 4 (mod 32), 72 = 8 (mod 32): conflict-free frags.
// One __syncthreads per k-tile; K/V fetch overlaps MMA work; K/V staged once
// per 128 Q rows (2x the amortization of the 64-row version).
// ---------------------------------------------------------------------------
#define AP 68
#define VP 72

__global__ __launch_bounds__(256)
void attn_tc(const float* __restrict__ cplx, const float* __restrict__ cpen_p)
{
    extern __shared__ uint32_t smem[];
    uint32_t* Qs  = smem;                 // 128*AP
    uint32_t* Ks0 = Qs  + 128 * AP;
    uint32_t* Ks1 = Ks0 + 64 * AP;
    uint32_t* Vs0 = Ks1 + 64 * AP;
    uint32_t* Vs1 = Vs0 + 64 * VP;
    uint32_t* Ps  = Vs1 + 64 * VP;        // 128*AP

    const int tid  = threadIdx.x;
    const int lane = tid & 31;
    const int w    = tid >> 5;
    const int r    = lane >> 2;
    const int j    = lane & 3;
    const int rb   = w * 16;              // warp row base (0..112)

    const int qt = (gridDim.x - 1) - blockIdx.x;   // heavy tiles first
    const int bh = blockIdx.y;
    const int b  = bh >> 4;
    const int h  = bh & 15;
    const float cpen = __ldg(cpen_p);

    const float* Qg = g_Q + (size_t)bh * S_ * DK_;
    const float* Kg = g_K + (size_t)bh * S_ * DK_;
    const float* Vg = g_V + (size_t)bh * S_ * DK_;

    // Q staging: 256 thr, each 32 floats of one row
    const int qrow  = tid >> 1;           // 0..127
    const int qhalf = (tid & 1) * 32;
    const uint32_t qdst = (uint32_t)__cvta_generic_to_shared(&Qs[qrow * AP + qhalf]);

    // K/V staging: 256 thr, each 16 floats of one row
    const int krow = tid >> 2;            // 0..63
    const int kq   = (tid & 3) * 16;
    uint32_t kdst[2] = {
        (uint32_t)__cvta_generic_to_shared(&Ks0[krow * AP + kq]),
        (uint32_t)__cvta_generic_to_shared(&Ks1[krow * AP + kq]) };
    uint32_t vdst[2] = {
        (uint32_t)__cvta_generic_to_shared(&Vs0[krow * VP + kq]),
        (uint32_t)__cvta_generic_to_shared(&Vs1[krow * VP + kq]) };

    auto stage_kv = [&](int kt, int buf) {
        const float* ks = Kg + (size_t)(kt * 64 + krow) * DK_ + kq;
        const float* vs = Vg + (size_t)(kt * 64 + krow) * DK_ + kq;
#pragma unroll
        for (int q = 0; q < 4; ++q) {
            cp16(kdst[buf] + q * 16, ks + q * 4);
            cp16(vdst[buf] + q * 16, vs + q * 4);
        }
    };

    // prologue: Q tile + first K/V tile in group 0
    {
        const float* qs = Qg + (size_t)(qt * 128 + qrow) * DK_ + qhalf;
#pragma unroll
        for (int q = 0; q < 8; ++q) cp16(qdst + q * 16, qs + q * 4);
        stage_kv(0, 0);
        cp_commit();
    }

    float o[8][4];
    float m_lo = -1e30f, m_hi = -1e30f, l_lo = 0.0f, l_hi = 0.0f;
#pragma unroll
    for (int nt = 0; nt < 8; ++nt)
#pragma unroll
        for (int c = 0; c < 4; ++c) o[nt][c] = 0.0f;

    const int nkt = 2 * qt + 2;
    for (int kt = 0; kt < nkt; ++kt) {
        cp_wait<0>();
        __syncthreads();   // staged data visible; prior compute done everywhere

        if (kt + 1 < nkt) { stage_kv(kt + 1, (kt + 1) & 1); cp_commit(); }

        const uint32_t* Kb = (kt & 1) ? Ks1 : Ks0;
        const uint32_t* Vb = (kt & 1) ? Vs1 : Vs0;

        // ---- S = Q K^T  (warp: 16 rows x 64 keys) ----
        float s[8][4];
#pragma unroll
        for (int nt = 0; nt < 8; ++nt)
#pragma unroll
            for (int c = 0; c < 4; ++c) s[nt][c] = 0.0f;

#pragma unroll
        for (int ks = 0; ks < 8; ++ks) {
            const int k = ks * 8 + j;
            uint32_t a0 = Qs[(rb + r) * AP + k];
            uint32_t a1 = Qs[(rb + r + 8) * AP + k];
            uint32_t a2 = Qs[(rb + r) * AP + k + 4];
            uint32_t a3 = Qs[(rb + r + 8) * AP + k + 4];
#pragma unroll
            for (int nt = 0; nt < 8; ++nt) {
                uint32_t b0 = Kb[(nt * 8 + r) * AP + k];
                uint32_t b1 = Kb[(nt * 8 + r) * AP + k + 4];
                mma_tf32(s[nt][0], s[nt][1], s[nt][2], s[nt][3], a0, a1, a2, a3, b0, b1);
            }
        }

        // ---- scale + penalty + causal mask ----
        const int rowg_lo = qt * 128 + rb + r;
        const int rowg_hi = rowg_lo + 8;
#pragma unroll
        for (int nt = 0; nt < 8; ++nt) {
            const int colg = kt * 64 + nt * 8 + 2 * j;
            const float2 cv = *(const float2*)&cplx[b * S_ + colg];
            const float p0 = cpen * cv.x, p1 = cpen * cv.y;
            s[nt][0] = s[nt][0] * 0.125f - p0;
            s[nt][1] = s[nt][1] * 0.125f - p1;
            s[nt][2] = s[nt][2] * 0.125f - p0;
            s[nt][3] = s[nt][3] * 0.125f - p1;
            if (kt >= 2 * qt) {          // (possibly) diagonal k-tile
                if (colg     > rowg_lo) s[nt][0] = -1e9f;
                if (colg + 1 > rowg_lo) s[nt][1] = -1e9f;
                if (colg     > rowg_hi) s[nt][2] = -1e9f;
                if (colg + 1 > rowg_hi) s[nt][3] = -1e9f;
            }
        }

        // ---- online softmax ----
        float mx_lo = -1e30f, mx_hi = -1e30f;
#pragma unroll
        for (int nt = 0; nt < 8; ++nt) {
            mx_lo = fmaxf(mx_lo, fmaxf(s[nt][0], s[nt][1]));
            mx_hi = fmaxf(mx_hi, fmaxf(s[nt][2], s[nt][3]));
        }
        mx_lo = fmaxf(mx_lo, __shfl_xor_sync(0xffffffffu, mx_lo, 1));
        mx_lo = fmaxf(mx_lo, __shfl_xor_sync(0xffffffffu, mx_lo, 2));
        mx_hi = fmaxf(mx_hi, __shfl_xor_sync(0xffffffffu, mx_hi, 1));
        mx_hi = fmaxf(mx_hi, __shfl_xor_sync(0xffffffffu, mx_hi, 2));

        const float nm_lo = fmaxf(m_lo, mx_lo);
        const float nm_hi = fmaxf(m_hi, mx_hi);
        const float al_lo = __expf(m_lo - nm_lo);
        const float al_hi = __expf(m_hi - nm_hi);
        m_lo = nm_lo; m_hi = nm_hi;

        float sum_lo = 0.0f, sum_hi = 0.0f;
#pragma unroll
        for (int nt = 0; nt < 8; ++nt) {
            s[nt][0] = __expf(s[nt][0] - nm_lo);
            s[nt][1] = __expf(s[nt][1] - nm_lo);
            s[nt][2] = __expf(s[nt][2] - nm_hi);
            s[nt][3] = __expf(s[nt][3] - nm_hi);
            sum_lo += s[nt][0] + s[nt][1];
            sum_hi += s[nt][2] + s[nt][3];
            uint2 plo = make_uint2(f2tf(s[nt][0]), f2tf(s[nt][1]));
            uint2 phi = make_uint2(f2tf(s[nt][2]), f2tf(s[nt][3]));
            *(uint2*)&Ps[(rb + r) * AP + nt * 8 + 2 * j]     = plo;
            *(uint2*)&Ps[(rb + r + 8) * AP + nt * 8 + 2 * j] = phi;
        }
        sum_lo += __shfl_xor_sync(0xffffffffu, sum_lo, 1);
        sum_lo += __shfl_xor_sync(0xffffffffu, sum_lo, 2);
        sum_hi += __shfl_xor_sync(0xffffffffu, sum_hi, 1);
        sum_hi += __shfl_xor_sync(0xffffffffu, sum_hi, 2);
        l_lo = l_lo * al_lo + sum_lo;
        l_hi = l_hi * al_hi + sum_hi;

#pragma unroll
        for (int nt = 0; nt < 8; ++nt) {
            o[nt][0] *= al_lo; o[nt][1] *= al_lo;
            o[nt][2] *= al_hi; o[nt][3] *= al_hi;
        }
        __syncwarp();   // P (warp-private rows) visible within warp

        // ---- O += P V  (V row-major: B[k=key][n=d], pitch 72) ----
#pragma unroll
        for (int ks = 0; ks < 8; ++ks) {
            const int k = ks * 8 + j;
            uint32_t a0 = Ps[(rb + r) * AP + k];
            uint32_t a1 = Ps[(rb + r + 8) * AP + k];
            uint32_t a2 = Ps[(rb + r) * AP + k + 4];
            uint32_t a3 = Ps[(rb + r + 8) * AP + k + 4];
            const int krow0 = (ks * 8 + j) * VP;
            const int krow1 = (ks * 8 + j + 4) * VP;
#pragma unroll
            for (int nt = 0; nt < 8; ++nt) {
                uint32_t b0 = Vb[krow0 + nt * 8 + r];
                uint32_t b1 = Vb[krow1 + nt * 8 + r];
                mma_tf32(o[nt][0], o[nt][1], o[nt][2], o[nt][3], a0, a1, a2, a3, b0, b1);
            }
        }
    }

    // ---- epilogue (ctx written tf32-rounded for the Wo GEMM) ----
    const float inv_lo = 1.0f / l_lo;
    const float inv_hi = 1.0f / l_hi;
    const int row_lo = qt * 128 + rb + r;
    const int row_hi = row_lo + 8;
#pragma unroll
    for (int nt = 0; nt < 8; ++nt) {
        const int gc = h * DK_ + nt * 8 + 2 * j;
        *(float2*)&g_ctx[(size_t)(b * S_ + row_lo) * D_ + gc] =
            make_float2(__uint_as_float(f2tf(o[nt][0] * inv_lo)),
                        __uint_as_float(f2tf(o[nt][1] * inv_lo)));
        *(float2*)&g_ctx[(size_t)(b * S_ + row_hi) * D_ + gc] =
            make_float2(__uint_as_float(f2tf(o[nt][2] * inv_hi)),
                        __uint_as_float(f2tf(o[nt][3] * inv_hi)));
    }
}

// ---------------------------------------------------------------------------
// LayerNorm over D=1024 with residual add: out = LN(g_proj + query)*g + b
// ---------------------------------------------------------------------------
__global__ __launch_bounds__(256)
void ln_resid(const float* __restrict__ resid, const float* __restrict__ gamma,
              const float* __restrict__ beta, float* __restrict__ out)
{
    __shared__ float rs[8], rq[8];
    const int row = blockIdx.x;
    const int tid = threadIdx.x;

    const float* xr = g_proj + (size_t)row * D_;
    const float* rr = resid  + (size_t)row * D_;

    float4 a = *(const float4*)&xr[tid * 4];
    float4 r = *(const float4*)&rr[tid * 4];
    float x0 = a.x + r.x, x1 = a.y + r.y, x2 = a.z + r.z, x3 = a.w + r.w;

    float s  = x0 + x1 + x2 + x3;
    float sq = x0 * x0 + x1 * x1 + x2 * x2 + x3 * x3;
#pragma unroll
    for (int off = 16; off >= 1; off >>= 1) {
        s  += __shfl_xor_sync(0xffffffffu, s,  off);
        sq += __shfl_xor_sync(0xffffffffu, sq, off);
    }
    const int wid = tid >> 5;
    if ((tid & 31) == 0) { rs[wid] = s; rq[wid] = sq; }
    __syncthreads();
    float tot = 0.0f, totq = 0.0f;
#pragma unroll
    for (int ww = 0; ww < 8; ++ww) { tot += rs[ww]; totq += rq[ww]; }

    const float mean = tot * (1.0f / D_);
    const float var  = totq * (1.0f / D_) - mean * mean;
    const float rstd = rsqrtf(var + 1e-5f);

    float4 g = *(const float4*)&gamma[tid * 4];
    float4 be = *(const float4*)&beta[tid * 4];
    float4 oo;
    oo.x = (x0 - mean) * rstd * g.x + be.x;
    oo.y = (x1 - mean) * rstd * g.y + be.y;
    oo.z = (x2 - mean) * rstd * g.z + be.z;
    oo.w = (x3 - mean) * rstd * g.w + be.w;
    *(float4*)&out[(size_t)row * D_ + tid * 4] = oo;
}

// ---------------------------------------------------------------------------
// kernel_launch
// ---------------------------------------------------------------------------
extern "C" void kernel_launch(void* const* d_in, const int* in_sizes, int n_in,
                              void* d_out, int out_size)
{
    (void)in_sizes; (void)n_in; (void)out_size;

    const float* query = (const float*)d_in[0];
    const float* key   = (const float*)d_in[1];
    const float* value = (const float*)d_in[2];
    const float* cplx  = (const float*)d_in[3];
    // d_in[4] = mask (bool tril) — deterministic, applied analytically
    const float* wq = (const float*)d_in[5];
    const float* bq = (const float*)d_in[6];
    const float* wk = (const float*)d_in[7];
    const float* bk = (const float*)d_in[8];
    const float* wv = (const float*)d_in[9];
    const float* bv = (const float*)d_in[10];
    const float* wo = (const float*)d_in[11];
    const float* bo = (const float*)d_in[12];
    const float* lng = (const float*)d_in[13];
    const float* lnb = (const float*)d_in[14];
    const float* cpen = (const float*)d_in[15];
    float* out = (float*)d_out;

    void *pQ, *pK, *pV, *pCtx, *pProj, *pRW, *pRX;
    cudaGetSymbolAddress(&pQ,    g_Q);
    cudaGetSymbolAddress(&pK,    g_K);
    cudaGetSymbolAddress(&pV,    g_V);
    cudaGetSymbolAddress(&pCtx,  g_ctx);
    cudaGetSymbolAddress(&pProj, g_proj);
    cudaGetSymbolAddress(&pRW,   g_rW);
    cudaGetSymbolAddress(&pRX,   g_rX);
    float* rW = (float*)pRW;
    float* rX = (float*)pRX;

    const int ATTN_SMEM =
        (128 * AP + 2 * 64 * AP + 2 * 64 * VP + 128 * AP) * 4;   // 141312
    cudaFuncSetAttribute(attn_tc, cudaFuncAttributeMaxDynamicSharedMemorySize,
                         ATTN_SMEM);

    // ---- pre-round weights & activations to tf32 (kills MMA-input bias) ----
    const int NW = D_ * D_;       // 1 M
    const int NX = BS_ * D_;      // 4 M
    round_pass<<<NW / 1024, 256>>>(wq, rW + 0 * (size_t)NW, NW);
    round_pass<<<NW / 1024, 256>>>(wk, rW + 1 * (size_t)NW, NW);
    round_pass<<<NW / 1024, 256>>>(wv, rW + 2 * (size_t)NW, NW);
    round_pass<<<NW / 1024, 256>>>(wo, rW + 3 * (size_t)NW, NW);
    round_pass<<<NX / 1024, 256>>>(query, rX + 0 * (size_t)NX, NX);
    round_pass<<<NX / 1024, 256>>>(key,   rX + 1 * (size_t)NX, NX);
    round_pass<<<NX / 1024, 256>>>(value, rX + 2 * (size_t)NX, NX);

    // Q/K/V projections merged into one launch (dense wave packing)
    dim3 gg3(D_ / 128, BS_ / 128, 3);   // (8, 32, 3)
    gemm_qkv<<<gg3, 256>>>(rX, rW, bq, bk, bv,
                           (float*)pQ, (float*)pK, (float*)pV);

    // Flash attention -> g_ctx (tf32-rounded)
    dim3 ga(S_ / 128, B_ * H_);     // (16, 32)
    attn_tc<<<ga, 256, ATTN_SMEM>>>(cplx, cpen);

    // Output projection -> g_proj (exact fp32)
    dim3 gg(D_ / 128, BS_ / 128);   // (8, 32)
    gemm_tc0<<<gg, 256>>>((const float*)pCtx, rW + 3 * (size_t)NW, bo, (float*)pProj);

    // Residual + LayerNorm -> d_out
    ln_resid<<<BS_, 256>>>(query, lng, lnb, out);
}

// round 13
// speedup vs baseline: 1.9272x; 1.0129x over previous
#include <cuda_runtime.h>
#include <math.h>
#include <stdint.h>

// Problem constants
#define B_   2
#define S_   2048
#define D_   1024
#define H_   16
#define DK_  64
#define BS_  (B_ * S_)   // 4096

// ---------------------------------------------------------------------------
// Device scratch (no allocations allowed -> __device__ globals)
// ---------------------------------------------------------------------------
__device__ float g_Q[B_ * H_ * S_ * DK_];     // [B,H,S,DK]  (tf32-rounded)
__device__ float g_K[B_ * H_ * S_ * DK_];
__device__ float g_V[B_ * H_ * S_ * DK_];
__device__ float g_ctx[B_ * S_ * D_];         // [B,S,D]     (tf32-rounded)
__device__ float g_proj[B_ * S_ * D_];        // out-proj result (exact fp32)
__device__ float g_rW[4 * D_ * D_];           // rounded wq,wk,wv,wo
__device__ float g_rX[3 * BS_ * D_];          // rounded query,key,value

// ---------------------------------------------------------------------------
// tf32 + cp.async helpers
// ---------------------------------------------------------------------------
__device__ __forceinline__ uint32_t f2tf(float f) {
    uint32_t u;
    asm("cvt.rna.tf32.f32 %0, %1;" : "=r"(u) : "f"(f));
    return u;
}
__device__ __forceinline__ uint4 f2tf4(float4 v) {
    uint4 u;
    u.x = f2tf(v.x); u.y = f2tf(v.y); u.z = f2tf(v.z); u.w = f2tf(v.w);
    return u;
}
__device__ __forceinline__ void cp16(uint32_t dst, const void* src) {
    asm volatile("cp.async.cg.shared.global [%0], [%1], 16;\n"
                 :: "r"(dst), "l"(src));
}
__device__ __forceinline__ void cp_commit() {
    asm volatile("cp.async.commit_group;\n");
}
template <int N>
__device__ __forceinline__ void cp_wait() {
    asm volatile("cp.async.wait_group %0;\n" :: "n"(N));
}
// D(16x8,f32) += A(16x8,tf32,row) * B(8x8,tf32,col)
__device__ __forceinline__ void mma_tf32(float& d0, float& d1, float& d2, float& d3,
                                         uint32_t a0, uint32_t a1, uint32_t a2, uint32_t a3,
                                         uint32_t b0, uint32_t b1) {
    asm volatile(
        "mma.sync.aligned.m16n8k8.row.col.f32.tf32.tf32.f32 "
        "{%0,%1,%2,%3}, {%4,%5,%6,%7}, {%8,%9}, {%0,%1,%2,%3};\n"
        : "+f"(d0), "+f"(d1), "+f"(d2), "+f"(d3)
        : "r"(a0), "r"(a1), "r"(a2), "r"(a3), "r"(b0), "r"(b1));
}

// ---------------------------------------------------------------------------
// Elementwise tf32 rounding pass (src -> dst), n multiple of 4
// ---------------------------------------------------------------------------
__global__ void round_pass(const float* __restrict__ src, float* __restrict__ dst,
                           int n)
{
    const int i = (blockIdx.x * blockDim.x + threadIdx.x) * 4;
    if (i < n) {
        uint4 u = f2tf4(*(const float4*)(src + i));
        *(float4*)(dst + i) = make_float4(__uint_as_float(u.x), __uint_as_float(u.y),
                                          __uint_as_float(u.z), __uint_as_float(u.w));
    }
}

// ---------------------------------------------------------------------------
// tf32 tensor-core GEMM body: Y[m][n] = sum_k A[m][k]*W[n][k] + bias[n]
//   A, W already tf32-rounded fp32. MODE 0: row-major out (exact fp32);
//   MODE 1: out scattered to [B,H,S,DK], tf32-rounded.
// CTA 128x128, 256 thr, warp tile 64x32. k32 chunks, 2-stage cp.async,
// ONE __syncthreads per chunk (32 barriers total), 64 HMMA/warp per barrier.
// smem pitch 36 (= 4 mod 32 -> conflict-free fragment gathers).
// ---------------------------------------------------------------------------
#define GP 36   // 32 data + 4 pad

template <int MODE>
__device__ __forceinline__
void gemm_body(const float* __restrict__ A, const float* __restrict__ W,
               const float* __restrict__ bias, float* __restrict__ out,
               uint32_t (*As)[128 * GP], uint32_t (*Bs)[128 * GP])
{
    const int tid  = threadIdx.x;
    const int lane = tid & 31;
    const int w    = tid >> 5;
    const int wm   = w & 1;
    const int wn   = w >> 1;
    const int row0 = blockIdx.y * 128;
    const int col0 = blockIdx.x * 128;
    const int r = lane >> 2;
    const int j = lane & 3;

    // loader mapping: thread -> (row, 16-float quarter of the 32-float chunk)
    const int lrow = tid & 127;
    const int lkq  = (tid >> 7) << 4;   // 0 or 16

    const float* Aptr = A + (size_t)(row0 + lrow) * D_ + lkq;
    const float* Wptr = W + (size_t)(col0 + lrow) * D_ + lkq;

    uint32_t sA[2], sB[2];
#pragma unroll
    for (int s = 0; s < 2; ++s) {
        sA[s] = (uint32_t)__cvta_generic_to_shared(&As[s][lrow * GP + lkq]);
        sB[s] = (uint32_t)__cvta_generic_to_shared(&Bs[s][lrow * GP + lkq]);
    }

    float acc[4][4][4];
#pragma unroll
    for (int mt = 0; mt < 4; ++mt)
#pragma unroll
        for (int nt = 0; nt < 4; ++nt)
#pragma unroll
            for (int c = 0; c < 4; ++c) acc[mt][nt][c] = 0.0f;

    // prologue: stage chunk 0 into buffer 0
    {
#pragma unroll
        for (int q = 0; q < 4; ++q) {
            cp16(sA[0] + q * 16, Aptr + q * 4);
            cp16(sB[0] + q * 16, Wptr + q * 4);
        }
        cp_commit();
    }

    const int arow = (wm * 64 + r) * GP;
    const int brow = (wn * 32 + r) * GP;

    constexpr int TILES = D_ / 32;   // 32
    for (int t = 0; t < TILES; ++t) {
        cp_wait<0>();
        __syncthreads();   // staged chunk t visible; prior compute (t-1) done

        if (t + 1 < TILES) {
            const int nb = (t + 1) & 1;
            const float* a  = Aptr + (t + 1) * 32;
            const float* wv = Wptr + (t + 1) * 32;
#pragma unroll
            for (int q = 0; q < 4; ++q) {
                cp16(sA[nb] + q * 16, a + q * 4);
                cp16(sB[nb] + q * 16, wv + q * 4);
            }
            cp_commit();
        }

        const uint32_t* Ab = As[t & 1];
        const uint32_t* Bb = Bs[t & 1];
#pragma unroll
        for (int ss = 0; ss < 4; ++ss) {
            const int k = ss * 8 + j;
            uint32_t af[4][4];
#pragma unroll
            for (int mt = 0; mt < 4; ++mt) {
                const int base = arow + mt * 16 * GP;
                af[mt][0] = Ab[base + k];
                af[mt][1] = Ab[base + 8 * GP + k];
                af[mt][2] = Ab[base + k + 4];
                af[mt][3] = Ab[base + 8 * GP + k + 4];
            }
#pragma unroll
            for (int nt = 0; nt < 4; ++nt) {
                const int base = brow + nt * 8 * GP;
                uint32_t b0 = Bb[base + k];
                uint32_t b1 = Bb[base + k + 4];
#pragma unroll
                for (int mt = 0; mt < 4; ++mt)
                    mma_tf32(acc[mt][nt][0], acc[mt][nt][1], acc[mt][nt][2], acc[mt][nt][3],
                             af[mt][0], af[mt][1], af[mt][2], af[mt][3], b0, b1);
            }
        }
        // no trailing barrier: next iteration's top barrier orders buffer reuse
    }

    // epilogue
#pragma unroll
    for (int mt = 0; mt < 4; ++mt) {
        const int gr = row0 + wm * 64 + mt * 16 + r;
#pragma unroll
        for (int nt = 0; nt < 4; ++nt) {
            const int gc = col0 + wn * 32 + nt * 8 + 2 * j;
            const float2 bb = *(const float2*)&bias[gc];
            float2 v0 = make_float2(acc[mt][nt][0] + bb.x, acc[mt][nt][1] + bb.y);
            float2 v1 = make_float2(acc[mt][nt][2] + bb.x, acc[mt][nt][3] + bb.y);
            if (MODE == 0) {
                *(float2*)&out[(size_t)gr * D_ + gc]       = v0;
                *(float2*)&out[(size_t)(gr + 8) * D_ + gc] = v1;
            } else {
                // round to tf32 (consumed by attention MMAs)
                v0 = make_float2(__uint_as_float(f2tf(v0.x)), __uint_as_float(f2tf(v0.y)));
                v1 = make_float2(__uint_as_float(f2tf(v1.x)), __uint_as_float(f2tf(v1.y)));
                const int h  = gc >> 6;
                const int dk = gc & 63;
                const int b0i = gr >> 11, s0 = gr & (S_ - 1);
                const int gr1 = gr + 8;
                const int b1i = gr1 >> 11, s1 = gr1 & (S_ - 1);
                *(float2*)&out[(((size_t)(b0i * H_ + h) * S_) + s0) * DK_ + dk] = v0;
                *(float2*)&out[(((size_t)(b1i * H_ + h) * S_) + s1) * DK_ + dk] = v1;
            }
        }
    }
}

// wo projection: single GEMM, row-major fp32 out
__global__ __launch_bounds__(256, 2)
void gemm_tc0(const float* __restrict__ A, const float* __restrict__ W,
              const float* __restrict__ bias, float* __restrict__ out)
{
    __shared__ uint32_t As[2][128 * GP];
    __shared__ uint32_t Bs[2][128 * GP];
    gemm_body<0>(A, W, bias, out, As, Bs);
}

// QKV projections merged: blockIdx.z selects {q,k,v} -> dense wave packing
__global__ __launch_bounds__(256, 2)
void gemm_qkv(const float* __restrict__ X, const float* __restrict__ W4,
              const float* __restrict__ bq, const float* __restrict__ bk,
              const float* __restrict__ bv,
              float* __restrict__ oq, float* __restrict__ ok,
              float* __restrict__ ov)
{
    __shared__ uint32_t As[2][128 * GP];
    __shared__ uint32_t Bs[2][128 * GP];
    const int z = blockIdx.z;
    const size_t NX = (size_t)BS_ * D_;
    const size_t NW = (size_t)D_ * D_;
    const float* A    = X  + z * NX;
    const float* W    = W4 + z * NW;
    const float* bias = (z == 0) ? bq : (z == 1) ? bk : bv;
    float*       out  = (z == 0) ? oq : (z == 1) ? ok : ov;
    gemm_body<1>(A, W, bias, out, As, Bs);
}

// ---------------------------------------------------------------------------
// Flash attention, tf32 tensor cores, cp.async double-buffered K/V.
// CTA 256 thr (8 warps), Q tile 128 rows, K tile 64 keys; warp = one m16 slice.
// smem (dynamic, 138 KB): Qs[128][68], Ks[2][64][68], Vs[2][64][72] (row-major),
// Ps[128][68]. Pitches 68 = 4 (mod 32), 72 = 8 (mod 32): conflict-free frags.
// One __syncthreads per k-tile; K/V fetch overlaps MMA work.
// ---------------------------------------------------------------------------
#define AP 68
#define VP 72

__global__ __launch_bounds__(256)
void attn_tc(const float* __restrict__ cplx, const float* __restrict__ cpen_p)
{
    extern __shared__ uint32_t smem[];
    uint32_t* Qs  = smem;                 // 128*AP
    uint32_t* Ks0 = Qs  + 128 * AP;
    uint32_t* Ks1 = Ks0 + 64 * AP;
    uint32_t* Vs0 = Ks1 + 64 * AP;
    uint32_t* Vs1 = Vs0 + 64 * VP;
    uint32_t* Ps  = Vs1 + 64 * VP;        // 128*AP

    const int tid  = threadIdx.x;
    const int lane = tid & 31;
    const int w    = tid >> 5;
    const int r    = lane >> 2;
    const int j    = lane & 3;
    const int rb   = w * 16;              // warp row base (0..112)

    const int qt = (gridDim.x - 1) - blockIdx.x;   // heavy tiles first
    const int bh = blockIdx.y;
    const int b  = bh >> 4;
    const int h  = bh & 15;
    const float cpen = __ldg(cpen_p);

    const float* Qg = g_Q + (size_t)bh * S_ * DK_;
    const float* Kg = g_K + (size_t)bh * S_ * DK_;
    const float* Vg = g_V + (size_t)bh * S_ * DK_;

    // Q staging: 256 thr, each 32 floats of one row
    const int qrow  = tid >> 1;           // 0..127
    const int qhalf = (tid & 1) * 32;
    const uint32_t qdst = (uint32_t)__cvta_generic_to_shared(&Qs[qrow * AP + qhalf]);

    // K/V staging: 256 thr, each 16 floats of one row
    const int krow = tid >> 2;            // 0..63
    const int kq   = (tid & 3) * 16;
    uint32_t kdst[2] = {
        (uint32_t)__cvta_generic_to_shared(&Ks0[krow * AP + kq]),
        (uint32_t)__cvta_generic_to_shared(&Ks1[krow * AP + kq]) };
    uint32_t vdst[2] = {
        (uint32_t)__cvta_generic_to_shared(&Vs0[krow * VP + kq]),
        (uint32_t)__cvta_generic_to_shared(&Vs1[krow * VP + kq]) };

    auto stage_kv = [&](int kt, int buf) {
        const float* ks = Kg + (size_t)(kt * 64 + krow) * DK_ + kq;
        const float* vs = Vg + (size_t)(kt * 64 + krow) * DK_ + kq;
#pragma unroll
        for (int q = 0; q < 4; ++q) {
            cp16(kdst[buf] + q * 16, ks + q * 4);
            cp16(vdst[buf] + q * 16, vs + q * 4);
        }
    };

    // prologue: Q tile + first K/V tile in group 0
    {
        const float* qs = Qg + (size_t)(qt * 128 + qrow) * DK_ + qhalf;
#pragma unroll
        for (int q = 0; q < 8; ++q) cp16(qdst + q * 16, qs + q * 4);
        stage_kv(0, 0);
        cp_commit();
    }

    float o[8][4];
    float m_lo = -1e30f, m_hi = -1e30f, l_lo = 0.0f, l_hi = 0.0f;
#pragma unroll
    for (int nt = 0; nt < 8; ++nt)
#pragma unroll
        for (int c = 0; c < 4; ++c) o[nt][c] = 0.0f;

    const int nkt = 2 * qt + 2;
    for (int kt = 0; kt < nkt; ++kt) {
        cp_wait<0>();
        __syncthreads();   // staged data visible; prior compute done everywhere

        if (kt + 1 < nkt) { stage_kv(kt + 1, (kt + 1) & 1); cp_commit(); }

        const uint32_t* Kb = (kt & 1) ? Ks1 : Ks0;
        const uint32_t* Vb = (kt & 1) ? Vs1 : Vs0;

        // ---- S = Q K^T  (warp: 16 rows x 64 keys) ----
        float s[8][4];
#pragma unroll
        for (int nt = 0; nt < 8; ++nt)
#pragma unroll
            for (int c = 0; c < 4; ++c) s[nt][c] = 0.0f;

#pragma unroll
        for (int ks = 0; ks < 8; ++ks) {
            const int k = ks * 8 + j;
            uint32_t a0 = Qs[(rb + r) * AP + k];
            uint32_t a1 = Qs[(rb + r + 8) * AP + k];
            uint32_t a2 = Qs[(rb + r) * AP + k + 4];
            uint32_t a3 = Qs[(rb + r + 8) * AP + k + 4];
#pragma unroll
            for (int nt = 0; nt < 8; ++nt) {
                uint32_t b0 = Kb[(nt * 8 + r) * AP + k];
                uint32_t b1 = Kb[(nt * 8 + r) * AP + k + 4];
                mma_tf32(s[nt][0], s[nt][1], s[nt][2], s[nt][3], a0, a1, a2, a3, b0, b1);
            }
        }

        // ---- scale + penalty + causal mask ----
        const int rowg_lo = qt * 128 + rb + r;
        const int rowg_hi = rowg_lo + 8;
#pragma unroll
        for (int nt = 0; nt < 8; ++nt) {
            const int colg = kt * 64 + nt * 8 + 2 * j;
            const float2 cv = *(const float2*)&cplx[b * S_ + colg];
            const float p0 = cpen * cv.x, p1 = cpen * cv.y;
            s[nt][0] = s[nt][0] * 0.125f - p0;
            s[nt][1] = s[nt][1] * 0.125f - p1;
            s[nt][2] = s[nt][2] * 0.125f - p0;
            s[nt][3] = s[nt][3] * 0.125f - p1;
            if (kt >= 2 * qt) {          // (possibly) diagonal k-tile
                if (colg     > rowg_lo) s[nt][0] = -1e9f;
                if (colg + 1 > rowg_lo) s[nt][1] = -1e9f;
                if (colg     > rowg_hi) s[nt][2] = -1e9f;
                if (colg + 1 > rowg_hi) s[nt][3] = -1e9f;
            }
        }

        // ---- online softmax ----
        float mx_lo = -1e30f, mx_hi = -1e30f;
#pragma unroll
        for (int nt = 0; nt < 8; ++nt) {
            mx_lo = fmaxf(mx_lo, fmaxf(s[nt][0], s[nt][1]));
            mx_hi = fmaxf(mx_hi, fmaxf(s[nt][2], s[nt][3]));
        }
        mx_lo = fmaxf(mx_lo, __shfl_xor_sync(0xffffffffu, mx_lo, 1));
        mx_lo = fmaxf(mx_lo, __shfl_xor_sync(0xffffffffu, mx_lo, 2));
        mx_hi = fmaxf(mx_hi, __shfl_xor_sync(0xffffffffu, mx_hi, 1));
        mx_hi = fmaxf(mx_hi, __shfl_xor_sync(0xffffffffu, mx_hi, 2));

        const float nm_lo = fmaxf(m_lo, mx_lo);
        const float nm_hi = fmaxf(m_hi, mx_hi);
        const float al_lo = __expf(m_lo - nm_lo);
        const float al_hi = __expf(m_hi - nm_hi);
        m_lo = nm_lo; m_hi = nm_hi;

        float sum_lo = 0.0f, sum_hi = 0.0f;
#pragma unroll
        for (int nt = 0; nt < 8; ++nt) {
            s[nt][0] = __expf(s[nt][0] - nm_lo);
            s[nt][1] = __expf(s[nt][1] - nm_lo);
            s[nt][2] = __expf(s[nt][2] - nm_hi);
            s[nt][3] = __expf(s[nt][3] - nm_hi);
            sum_lo += s[nt][0] + s[nt][1];
            sum_hi += s[nt][2] + s[nt][3];
            uint2 plo = make_uint2(f2tf(s[nt][0]), f2tf(s[nt][1]));
            uint2 phi = make_uint2(f2tf(s[nt][2]), f2tf(s[nt][3]));
            *(uint2*)&Ps[(rb + r) * AP + nt * 8 + 2 * j]     = plo;
            *(uint2*)&Ps[(rb + r + 8) * AP + nt * 8 + 2 * j] = phi;
        }
        sum_lo += __shfl_xor_sync(0xffffffffu, sum_lo, 1);
        sum_lo += __shfl_xor_sync(0xffffffffu, sum_lo, 2);
        sum_hi += __shfl_xor_sync(0xffffffffu, sum_hi, 1);
        sum_hi += __shfl_xor_sync(0xffffffffu, sum_hi, 2);
        l_lo = l_lo * al_lo + sum_lo;
        l_hi = l_hi * al_hi + sum_hi;

#pragma unroll
        for (int nt = 0; nt < 8; ++nt) {
            o[nt][0] *= al_lo; o[nt][1] *= al_lo;
            o[nt][2] *= al_hi; o[nt][3] *= al_hi;
        }
        __syncwarp();   // P (warp-private rows) visible within warp

        // ---- O += P V  (V row-major: B[k=key][n=d], pitch 72) ----
#pragma unroll
        for (int ks = 0; ks < 8; ++ks) {
            const int k = ks * 8 + j;
            uint32_t a0 = Ps[(rb + r) * AP + k];
            uint32_t a1 = Ps[(rb + r + 8) * AP + k];
            uint32_t a2 = Ps[(rb + r) * AP + k + 4];
            uint32_t a3 = Ps[(rb + r + 8) * AP + k + 4];
            const int krow0 = (ks * 8 + j) * VP;
            const int krow1 = (ks * 8 + j + 4) * VP;
#pragma unroll
            for (int nt = 0; nt < 8; ++nt) {
                uint32_t b0 = Vb[krow0 + nt * 8 + r];
                uint32_t b1 = Vb[krow1 + nt * 8 + r];
                mma_tf32(o[nt][0], o[nt][1], o[nt][2], o[nt][3], a0, a1, a2, a3, b0, b1);
            }
        }
    }

    // ---- epilogue (ctx written tf32-rounded for the Wo GEMM) ----
    const float inv_lo = 1.0f / l_lo;
    const float inv_hi = 1.0f / l_hi;
    const int row_lo = qt * 128 + rb + r;
    const int row_hi = row_lo + 8;
#pragma unroll
    for (int nt = 0; nt < 8; ++nt) {
        const int gc = h * DK_ + nt * 8 + 2 * j;
        *(float2*)&g_ctx[(size_t)(b * S_ + row_lo) * D_ + gc] =
            make_float2(__uint_as_float(f2tf(o[nt][0] * inv_lo)),
                        __uint_as_float(f2tf(o[nt][1] * inv_lo)));
        *(float2*)&g_ctx[(size_t)(b * S_ + row_hi) * D_ + gc] =
            make_float2(__uint_as_float(f2tf(o[nt][2] * inv_hi)),
                        __uint_as_float(f2tf(o[nt][3] * inv_hi)));
    }
}

// ---------------------------------------------------------------------------
// LayerNorm over D=1024 with residual add: out = LN(g_proj + query)*g + b
// ---------------------------------------------------------------------------
__global__ __launch_bounds__(256)
void ln_resid(const float* __restrict__ resid, const float* __restrict__ gamma,
              const float* __restrict__ beta, float* __restrict__ out)
{
    __shared__ float rs[8], rq[8];
    const int row = blockIdx.x;
    const int tid = threadIdx.x;

    const float* xr = g_proj + (size_t)row * D_;
    const float* rr = resid  + (size_t)row * D_;

    float4 a = *(const float4*)&xr[tid * 4];
    float4 r = *(const float4*)&rr[tid * 4];
    float x0 = a.x + r.x, x1 = a.y + r.y, x2 = a.z + r.z, x3 = a.w + r.w;

    float s  = x0 + x1 + x2 + x3;
    float sq = x0 * x0 + x1 * x1 + x2 * x2 + x3 * x3;
#pragma unroll
    for (int off = 16; off >= 1; off >>= 1) {
        s  += __shfl_xor_sync(0xffffffffu, s,  off);
        sq += __shfl_xor_sync(0xffffffffu, sq, off);
    }
    const int wid = tid >> 5;
    if ((tid & 31) == 0) { rs[wid] = s; rq[wid] = sq; }
    __syncthreads();
    float tot = 0.0f, totq = 0.0f;
#pragma unroll
    for (int ww = 0; ww < 8; ++ww) { tot += rs[ww]; totq += rq[ww]; }

    const float mean = tot * (1.0f / D_);
    const float var  = totq * (1.0f / D_) - mean * mean;
    const float rstd = rsqrtf(var + 1e-5f);

    float4 g = *(const float4*)&gamma[tid * 4];
    float4 be = *(const float4*)&beta[tid * 4];
    float4 oo;
    oo.x = (x0 - mean) * rstd * g.x + be.x;
    oo.y = (x1 - mean) * rstd * g.y + be.y;
    oo.z = (x2 - mean) * rstd * g.z + be.z;
    oo.w = (x3 - mean) * rstd * g.w + be.w;
    *(float4*)&out[(size_t)row * D_ + tid * 4] = oo;
}

// ---------------------------------------------------------------------------
// kernel_launch
// ---------------------------------------------------------------------------
extern "C" void kernel_launch(void* const* d_in, const int* in_sizes, int n_in,
                              void* d_out, int out_size)
{
    (void)in_sizes; (void)n_in; (void)out_size;

    const float* query = (const float*)d_in[0];
    const float* key   = (const float*)d_in[1];
    const float* value = (const float*)d_in[2];
    const float* cplx  = (const float*)d_in[3];
    // d_in[4] = mask (bool tril) — deterministic, applied analytically
    const float* wq = (const float*)d_in[5];
    const float* bq = (const float*)d_in[6];
    const float* wk = (const float*)d_in[7];
    const float* bk = (const float*)d_in[8];
    const float* wv = (const float*)d_in[9];
    const float* bv = (const float*)d_in[10];
    const float* wo = (const float*)d_in[11];
    const float* bo = (const float*)d_in[12];
    const float* lng = (const float*)d_in[13];
    const float* lnb = (const float*)d_in[14];
    const float* cpen = (const float*)d_in[15];
    float* out = (float*)d_out;

    void *pQ, *pK, *pV, *pCtx, *pProj, *pRW, *pRX;
    cudaGetSymbolAddress(&pQ,    g_Q);
    cudaGetSymbolAddress(&pK,    g_K);
    cudaGetSymbolAddress(&pV,    g_V);
    cudaGetSymbolAddress(&pCtx,  g_ctx);
    cudaGetSymbolAddress(&pProj, g_proj);
    cudaGetSymbolAddress(&pRW,   g_rW);
    cudaGetSymbolAddress(&pRX,   g_rX);
    float* rW = (float*)pRW;
    float* rX = (float*)pRX;

    const int ATTN_SMEM =
        (128 * AP + 2 * 64 * AP + 2 * 64 * VP + 128 * AP) * 4;   // 141312
    cudaFuncSetAttribute(attn_tc, cudaFuncAttributeMaxDynamicSharedMemorySize,
                         ATTN_SMEM);

    // ---- pre-round weights & activations to tf32 (kills MMA-input bias) ----
    const int NW = D_ * D_;       // 1 M
    const int NX = BS_ * D_;      // 4 M
    round_pass<<<NW / 1024, 256>>>(wq, rW + 0 * (size_t)NW, NW);
    round_pass<<<NW / 1024, 256>>>(wk, rW + 1 * (size_t)NW, NW);
    round_pass<<<NW / 1024, 256>>>(wv, rW + 2 * (size_t)NW, NW);
    round_pass<<<NW / 1024, 256>>>(wo, rW + 3 * (size_t)NW, NW);
    round_pass<<<NX / 1024, 256>>>(query, rX + 0 * (size_t)NX, NX);
    round_pass<<<NX / 1024, 256>>>(key,   rX + 1 * (size_t)NX, NX);
    round_pass<<<NX / 1024, 256>>>(value, rX + 2 * (size_t)NX, NX);

    // Q/K/V projections merged into one launch (dense wave packing)
    dim3 gg3(D_ / 128, BS_ / 128, 3);   // (8, 32, 3)
    gemm_qkv<<<gg3, 256>>>(rX, rW, bq, bk, bv,
                           (float*)pQ, (float*)pK, (float*)pV);

    // Flash attention -> g_ctx (tf32-rounded)
    dim3 ga(S_ / 128, B_ * H_);     // (16, 32)
    attn_tc<<<ga, 256, ATTN_SMEM>>>(cplx, cpen);

    // Output projection -> g_proj (exact fp32)
    dim3 gg(D_ / 128, BS_ / 128);   // (8, 32)
    gemm_tc0<<<gg, 256>>>((const float*)pCtx, rW + 3 * (size_t)NW, bo, (float*)pProj);

    // Residual + LayerNorm -> d_out
    ln_resid<<<BS_, 256>>>(query, lng, lnb, out);
}

// round 14
// speedup vs baseline: 2.0445x; 1.0608x over previous
#include <cuda_runtime.h>
#include <math.h>
#include <stdint.h>

// Problem constants
#define B_   2
#define S_   2048
#define D_   1024
#define H_   16
#define DK_  64
#define BS_  (B_ * S_)   // 4096

// ---------------------------------------------------------------------------
// Device scratch (no allocations allowed -> __device__ globals)
// ---------------------------------------------------------------------------
__device__ float g_Q[B_ * H_ * S_ * DK_];     // [B,H,S,DK]  (tf32-rounded)
__device__ float g_K[B_ * H_ * S_ * DK_];
__device__ float g_V[B_ * H_ * S_ * DK_];
__device__ float g_ctx[B_ * S_ * D_];         // [B,S,D]     (tf32-rounded)
__device__ float g_proj[B_ * S_ * D_];        // out-proj result (exact fp32)
__device__ float g_rW[4 * D_ * D_];           // rounded wq,wk,wv,wo
__device__ float g_rX[3 * BS_ * D_];          // rounded query,key,value

// ---------------------------------------------------------------------------
// tf32 + cp.async helpers
// ---------------------------------------------------------------------------
__device__ __forceinline__ uint32_t f2tf(float f) {
    uint32_t u;
    asm("cvt.rna.tf32.f32 %0, %1;" : "=r"(u) : "f"(f));
    return u;
}
__device__ __forceinline__ uint4 f2tf4(float4 v) {
    uint4 u;
    u.x = f2tf(v.x); u.y = f2tf(v.y); u.z = f2tf(v.z); u.w = f2tf(v.w);
    return u;
}
__device__ __forceinline__ void cp16(uint32_t dst, const void* src) {
    asm volatile("cp.async.cg.shared.global [%0], [%1], 16;\n"
                 :: "r"(dst), "l"(src));
}
__device__ __forceinline__ void cp_commit() {
    asm volatile("cp.async.commit_group;\n");
}
template <int N>
__device__ __forceinline__ void cp_wait() {
    asm volatile("cp.async.wait_group %0;\n" :: "n"(N));
}
// D(16x8,f32) += A(16x8,tf32,row) * B(8x8,tf32,col)
__device__ __forceinline__ void mma_tf32(float& d0, float& d1, float& d2, float& d3,
                                         uint32_t a0, uint32_t a1, uint32_t a2, uint32_t a3,
                                         uint32_t b0, uint32_t b1) {
    asm volatile(
        "mma.sync.aligned.m16n8k8.row.col.f32.tf32.tf32.f32 "
        "{%0,%1,%2,%3}, {%4,%5,%6,%7}, {%8,%9}, {%0,%1,%2,%3};\n"
        : "+f"(d0), "+f"(d1), "+f"(d2), "+f"(d3)
        : "r"(a0), "r"(a1), "r"(a2), "r"(a3), "r"(b0), "r"(b1));
}

// ---------------------------------------------------------------------------
// One merged tf32 rounding pass over all 7 tensors (z selects tensor).
// z 0..3: weights (1M elems each); z 4..6: activations (4M elems each).
// ---------------------------------------------------------------------------
__global__ void round_all(const float* __restrict__ wq, const float* __restrict__ wk,
                          const float* __restrict__ wv, const float* __restrict__ wo,
                          const float* __restrict__ xq, const float* __restrict__ xk,
                          const float* __restrict__ xv,
                          float* __restrict__ rW, float* __restrict__ rX)
{
    const int z = blockIdx.z;
    const int NW = D_ * D_;
    const int NX = BS_ * D_;
    const int n  = (z < 4) ? NW : NX;
    const int i  = (blockIdx.x * blockDim.x + threadIdx.x) * 4;
    if (i >= n) return;
    const float* src;
    float* dst;
    switch (z) {
        case 0: src = wq; dst = rW;               break;
        case 1: src = wk; dst = rW + 1 * (size_t)NW; break;
        case 2: src = wv; dst = rW + 2 * (size_t)NW; break;
        case 3: src = wo; dst = rW + 3 * (size_t)NW; break;
        case 4: src = xq; dst = rX;               break;
        case 5: src = xk; dst = rX + 1 * (size_t)NX; break;
        default: src = xv; dst = rX + 2 * (size_t)NX; break;
    }
    uint4 u = f2tf4(*(const float4*)(src + i));
    *(float4*)(dst + i) = make_float4(__uint_as_float(u.x), __uint_as_float(u.y),
                                      __uint_as_float(u.z), __uint_as_float(u.w));
}

// ---------------------------------------------------------------------------
// tf32 tensor-core GEMM body: Y[m][n] = sum_k A[m][k]*W[n][k] + bias[n]
//   A, W already tf32-rounded fp32. MODE 0: row-major out (exact fp32);
//   MODE 1: out scattered to [B,H,S,DK], tf32-rounded.
// CTA 128x128, 256 thr, warp tile 64x32. k32 chunks, 2-stage cp.async,
// one __syncthreads per chunk. smem pitch 36 (conflict-free frag gathers).
// ---------------------------------------------------------------------------
#define GP 36   // 32 data + 4 pad

template <int MODE>
__device__ __forceinline__
void gemm_body(const float* __restrict__ A, const float* __restrict__ W,
               const float* __restrict__ bias, float* __restrict__ out,
               uint32_t (*As)[128 * GP], uint32_t (*Bs)[128 * GP])
{
    const int tid  = threadIdx.x;
    const int lane = tid & 31;
    const int w    = tid >> 5;
    const int wm   = w & 1;
    const int wn   = w >> 1;
    const int row0 = blockIdx.y * 128;
    const int col0 = blockIdx.x * 128;
    const int r = lane >> 2;
    const int j = lane & 3;

    const int lrow = tid & 127;
    const int lkq  = (tid >> 7) << 4;   // 0 or 16

    const float* Aptr = A + (size_t)(row0 + lrow) * D_ + lkq;
    const float* Wptr = W + (size_t)(col0 + lrow) * D_ + lkq;

    uint32_t sA[2], sB[2];
#pragma unroll
    for (int s = 0; s < 2; ++s) {
        sA[s] = (uint32_t)__cvta_generic_to_shared(&As[s][lrow * GP + lkq]);
        sB[s] = (uint32_t)__cvta_generic_to_shared(&Bs[s][lrow * GP + lkq]);
    }

    float acc[4][4][4];
#pragma unroll
    for (int mt = 0; mt < 4; ++mt)
#pragma unroll
        for (int nt = 0; nt < 4; ++nt)
#pragma unroll
            for (int c = 0; c < 4; ++c) acc[mt][nt][c] = 0.0f;

    // prologue: stage chunk 0 into buffer 0
    {
#pragma unroll
        for (int q = 0; q < 4; ++q) {
            cp16(sA[0] + q * 16, Aptr + q * 4);
            cp16(sB[0] + q * 16, Wptr + q * 4);
        }
        cp_commit();
    }

    const int arow = (wm * 64 + r) * GP;
    const int brow = (wn * 32 + r) * GP;

    constexpr int TILES = D_ / 32;   // 32
    for (int t = 0; t < TILES; ++t) {
        cp_wait<0>();
        __syncthreads();   // staged chunk t visible; prior compute (t-1) done

        if (t + 1 < TILES) {
            const int nb = (t + 1) & 1;
            const float* a  = Aptr + (t + 1) * 32;
            const float* wv = Wptr + (t + 1) * 32;
#pragma unroll
            for (int q = 0; q < 4; ++q) {
                cp16(sA[nb] + q * 16, a + q * 4);
                cp16(sB[nb] + q * 16, wv + q * 4);
            }
            cp_commit();
        }

        const uint32_t* Ab = As[t & 1];
        const uint32_t* Bb = Bs[t & 1];
#pragma unroll
        for (int ss = 0; ss < 4; ++ss) {
            const int k = ss * 8 + j;
            uint32_t af[4][4];
#pragma unroll
            for (int mt = 0; mt < 4; ++mt) {
                const int base = arow + mt * 16 * GP;
                af[mt][0] = Ab[base + k];
                af[mt][1] = Ab[base + 8 * GP + k];
                af[mt][2] = Ab[base + k + 4];
                af[mt][3] = Ab[base + 8 * GP + k + 4];
            }
#pragma unroll
            for (int nt = 0; nt < 4; ++nt) {
                const int base = brow + nt * 8 * GP;
                uint32_t b0 = Bb[base + k];
                uint32_t b1 = Bb[base + k + 4];
#pragma unroll
                for (int mt = 0; mt < 4; ++mt)
                    mma_tf32(acc[mt][nt][0], acc[mt][nt][1], acc[mt][nt][2], acc[mt][nt][3],
                             af[mt][0], af[mt][1], af[mt][2], af[mt][3], b0, b1);
            }
        }
        // no trailing barrier: next iteration's top barrier orders buffer reuse
    }

    // epilogue
#pragma unroll
    for (int mt = 0; mt < 4; ++mt) {
        const int gr = row0 + wm * 64 + mt * 16 + r;
#pragma unroll
        for (int nt = 0; nt < 4; ++nt) {
            const int gc = col0 + wn * 32 + nt * 8 + 2 * j;
            const float2 bb = *(const float2*)&bias[gc];
            float2 v0 = make_float2(acc[mt][nt][0] + bb.x, acc[mt][nt][1] + bb.y);
            float2 v1 = make_float2(acc[mt][nt][2] + bb.x, acc[mt][nt][3] + bb.y);
            if (MODE == 0) {
                *(float2*)&out[(size_t)gr * D_ + gc]       = v0;
                *(float2*)&out[(size_t)(gr + 8) * D_ + gc] = v1;
            } else {
                // round to tf32 (consumed by attention MMAs)
                v0 = make_float2(__uint_as_float(f2tf(v0.x)), __uint_as_float(f2tf(v0.y)));
                v1 = make_float2(__uint_as_float(f2tf(v1.x)), __uint_as_float(f2tf(v1.y)));
                const int h  = gc >> 6;
                const int dk = gc & 63;
                const int b0i = gr >> 11, s0 = gr & (S_ - 1);
                const int gr1 = gr + 8;
                const int b1i = gr1 >> 11, s1 = gr1 & (S_ - 1);
                *(float2*)&out[(((size_t)(b0i * H_ + h) * S_) + s0) * DK_ + dk] = v0;
                *(float2*)&out[(((size_t)(b1i * H_ + h) * S_) + s1) * DK_ + dk] = v1;
            }
        }
    }
}

// wo projection: single GEMM, row-major fp32 out
__global__ __launch_bounds__(256, 2)
void gemm_tc0(const float* __restrict__ A, const float* __restrict__ W,
              const float* __restrict__ bias, float* __restrict__ out)
{
    __shared__ uint32_t As[2][128 * GP];
    __shared__ uint32_t Bs[2][128 * GP];
    gemm_body<0>(A, W, bias, out, As, Bs);
}

// QKV projections merged: blockIdx.z selects {q,k,v} -> dense wave packing
__global__ __launch_bounds__(256, 2)
void gemm_qkv(const float* __restrict__ X, const float* __restrict__ W4,
              const float* __restrict__ bq, const float* __restrict__ bk,
              const float* __restrict__ bv,
              float* __restrict__ oq, float* __restrict__ ok,
              float* __restrict__ ov)
{
    __shared__ uint32_t As[2][128 * GP];
    __shared__ uint32_t Bs[2][128 * GP];
    const int z = blockIdx.z;
    const size_t NX = (size_t)BS_ * D_;
    const size_t NW = (size_t)D_ * D_;
    const float* A    = X  + z * NX;
    const float* W    = W4 + z * NW;
    const float* bias = (z == 0) ? bq : (z == 1) ? bk : bv;
    float*       out  = (z == 0) ? oq : (z == 1) ? ok : ov;
    gemm_body<1>(A, W, bias, out, As, Bs);
}

// ---------------------------------------------------------------------------
// Flash attention, tf32 tensor cores, single-buffered K/V, 2 CTAs/SM.
// CTA 256 thr (8 warps), Q tile 128 rows, K tile 64 keys; warp = one m16 slice.
// smem (dynamic, 103 KB): Qs[128][68], Ks[64][68], Vs[64][72] (row-major),
// Ps[128][68]. Pitches 68 = 4 (mod 32), 72 = 8 (mod 32): conflict-free frags.
// 2 CTAs resident per SM: cross-CTA overlap hides the (now unbuffered) K/V
// staging latency and doubles the warps feeding the L1 crossbar + MUFU pipes.
// ---------------------------------------------------------------------------
#define AP 68
#define VP 72

__global__ __launch_bounds__(256, 2)
void attn_tc(const float* __restrict__ cplx, const float* __restrict__ cpen_p)
{
    extern __shared__ uint32_t smem[];
    uint32_t* Qs = smem;                 // 128*AP
    uint32_t* Ks = Qs + 128 * AP;        // 64*AP
    uint32_t* Vs = Ks + 64 * AP;         // 64*VP
    uint32_t* Ps = Vs + 64 * VP;         // 128*AP

    const int tid  = threadIdx.x;
    const int lane = tid & 31;
    const int w    = tid >> 5;
    const int r    = lane >> 2;
    const int j    = lane & 3;
    const int rb   = w * 16;              // warp row base (0..112)

    const int qt = (gridDim.x - 1) - blockIdx.x;   // heavy tiles first
    const int bh = blockIdx.y;
    const int b  = bh >> 4;
    const int h  = bh & 15;
    const float cpen = __ldg(cpen_p);

    const float* Qg = g_Q + (size_t)bh * S_ * DK_;
    const float* Kg = g_K + (size_t)bh * S_ * DK_;
    const float* Vg = g_V + (size_t)bh * S_ * DK_;

    // Q staging: 256 thr, each 32 floats of one row
    const int qrow  = tid >> 1;           // 0..127
    const int qhalf = (tid & 1) * 32;
    const uint32_t qdst = (uint32_t)__cvta_generic_to_shared(&Qs[qrow * AP + qhalf]);

    // K/V staging: 256 thr, each 16 floats of one row
    const int krow = tid >> 2;            // 0..63
    const int kq   = (tid & 3) * 16;
    const uint32_t kdst = (uint32_t)__cvta_generic_to_shared(&Ks[krow * AP + kq]);
    const uint32_t vdst = (uint32_t)__cvta_generic_to_shared(&Vs[krow * VP + kq]);

    auto stage_kv = [&](int kt) {
        const float* ks = Kg + (size_t)(kt * 64 + krow) * DK_ + kq;
        const float* vs = Vg + (size_t)(kt * 64 + krow) * DK_ + kq;
#pragma unroll
        for (int q = 0; q < 4; ++q) {
            cp16(kdst + q * 16, ks + q * 4);
            cp16(vdst + q * 16, vs + q * 4);
        }
    };

    // prologue: Q tile + first K/V tile
    {
        const float* qs = Qg + (size_t)(qt * 128 + qrow) * DK_ + qhalf;
#pragma unroll
        for (int q = 0; q < 8; ++q) cp16(qdst + q * 16, qs + q * 4);
        stage_kv(0);
        cp_commit();
    }

    float o[8][4];
    float m_lo = -1e30f, m_hi = -1e30f, l_lo = 0.0f, l_hi = 0.0f;
#pragma unroll
    for (int nt = 0; nt < 8; ++nt)
#pragma unroll
        for (int c = 0; c < 4; ++c) o[nt][c] = 0.0f;

    const int nkt = 2 * qt + 2;
    for (int kt = 0; kt < nkt; ++kt) {
        cp_wait<0>();
        __syncthreads();   // staged K/V (+Q on iter 0) visible to all warps

        // ---- S = Q K^T  (warp: 16 rows x 64 keys) ----
        float s[8][4];
#pragma unroll
        for (int nt = 0; nt < 8; ++nt)
#pragma unroll
            for (int c = 0; c < 4; ++c) s[nt][c] = 0.0f;

#pragma unroll
        for (int ks = 0; ks < 8; ++ks) {
            const int k = ks * 8 + j;
            uint32_t a0 = Qs[(rb + r) * AP + k];
            uint32_t a1 = Qs[(rb + r + 8) * AP + k];
            uint32_t a2 = Qs[(rb + r) * AP + k + 4];
            uint32_t a3 = Qs[(rb + r + 8) * AP + k + 4];
#pragma unroll
            for (int nt = 0; nt < 8; ++nt) {
                uint32_t b0 = Ks[(nt * 8 + r) * AP + k];
                uint32_t b1 = Ks[(nt * 8 + r) * AP + k + 4];
                mma_tf32(s[nt][0], s[nt][1], s[nt][2], s[nt][3], a0, a1, a2, a3, b0, b1);
            }
        }

        // ---- scale + penalty + causal mask ----
        const int rowg_lo = qt * 128 + rb + r;
        const int rowg_hi = rowg_lo + 8;
#pragma unroll
        for (int nt = 0; nt < 8; ++nt) {
            const int colg = kt * 64 + nt * 8 + 2 * j;
            const float2 cv = *(const float2*)&cplx[b * S_ + colg];
            const float p0 = cpen * cv.x, p1 = cpen * cv.y;
            s[nt][0] = s[nt][0] * 0.125f - p0;
            s[nt][1] = s[nt][1] * 0.125f - p1;
            s[nt][2] = s[nt][2] * 0.125f - p0;
            s[nt][3] = s[nt][3] * 0.125f - p1;
            if (kt >= 2 * qt) {          // (possibly) diagonal k-tile
                if (colg     > rowg_lo) s[nt][0] = -1e9f;
                if (colg + 1 > rowg_lo) s[nt][1] = -1e9f;
                if (colg     > rowg_hi) s[nt][2] = -1e9f;
                if (colg + 1 > rowg_hi) s[nt][3] = -1e9f;
            }
        }

        // ---- online softmax ----
        float mx_lo = -1e30f, mx_hi = -1e30f;
#pragma unroll
        for (int nt = 0; nt < 8; ++nt) {
            mx_lo = fmaxf(mx_lo, fmaxf(s[nt][0], s[nt][1]));
            mx_hi = fmaxf(mx_hi, fmaxf(s[nt][2], s[nt][3]));
        }
        mx_lo = fmaxf(mx_lo, __shfl_xor_sync(0xffffffffu, mx_lo, 1));
        mx_lo = fmaxf(mx_lo, __shfl_xor_sync(0xffffffffu, mx_lo, 2));
        mx_hi = fmaxf(mx_hi, __shfl_xor_sync(0xffffffffu, mx_hi, 1));
        mx_hi = fmaxf(mx_hi, __shfl_xor_sync(0xffffffffu, mx_hi, 2));

        const float nm_lo = fmaxf(m_lo, mx_lo);
        const float nm_hi = fmaxf(m_hi, mx_hi);
        const float al_lo = __expf(m_lo - nm_lo);
        const float al_hi = __expf(m_hi - nm_hi);
        m_lo = nm_lo; m_hi = nm_hi;

        float sum_lo = 0.0f, sum_hi = 0.0f;
#pragma unroll
        for (int nt = 0; nt < 8; ++nt) {
            s[nt][0] = __expf(s[nt][0] - nm_lo);
            s[nt][1] = __expf(s[nt][1] - nm_lo);
            s[nt][2] = __expf(s[nt][2] - nm_hi);
            s[nt][3] = __expf(s[nt][3] - nm_hi);
            sum_lo += s[nt][0] + s[nt][1];
            sum_hi += s[nt][2] + s[nt][3];
            uint2 plo = make_uint2(f2tf(s[nt][0]), f2tf(s[nt][1]));
            uint2 phi = make_uint2(f2tf(s[nt][2]), f2tf(s[nt][3]));
            *(uint2*)&Ps[(rb + r) * AP + nt * 8 + 2 * j]     = plo;
            *(uint2*)&Ps[(rb + r + 8) * AP + nt * 8 + 2 * j] = phi;
        }
        sum_lo += __shfl_xor_sync(0xffffffffu, sum_lo, 1);
        sum_lo += __shfl_xor_sync(0xffffffffu, sum_lo, 2);
        sum_hi += __shfl_xor_sync(0xffffffffu, sum_hi, 1);
        sum_hi += __shfl_xor_sync(0xffffffffu, sum_hi, 2);
        l_lo = l_lo * al_lo + sum_lo;
        l_hi = l_hi * al_hi + sum_hi;

#pragma unroll
        for (int nt = 0; nt < 8; ++nt) {
            o[nt][0] *= al_lo; o[nt][1] *= al_lo;
            o[nt][2] *= al_hi; o[nt][3] *= al_hi;
        }
        __syncwarp();   // P (warp-private rows) visible within warp

        // ---- O += P V  (V row-major: B[k=key][n=d], pitch 72) ----
#pragma unroll
        for (int ks = 0; ks < 8; ++ks) {
            const int k = ks * 8 + j;
            uint32_t a0 = Ps[(rb + r) * AP + k];
            uint32_t a1 = Ps[(rb + r + 8) * AP + k];
            uint32_t a2 = Ps[(rb + r) * AP + k + 4];
            uint32_t a3 = Ps[(rb + r + 8) * AP + k + 4];
            const int krow0 = (ks * 8 + j) * VP;
            const int krow1 = (ks * 8 + j + 4) * VP;
#pragma unroll
            for (int nt = 0; nt < 8; ++nt) {
                uint32_t b0 = Vs[krow0 + nt * 8 + r];
                uint32_t b1 = Vs[krow1 + nt * 8 + r];
                mma_tf32(o[nt][0], o[nt][1], o[nt][2], o[nt][3], a0, a1, a2, a3, b0, b1);
            }
        }

        // all warps done reading Ks/Vs before restaging
        __syncthreads();
        if (kt + 1 < nkt) { stage_kv(kt + 1); cp_commit(); }
    }

    // ---- epilogue (ctx written tf32-rounded for the Wo GEMM) ----
    const float inv_lo = 1.0f / l_lo;
    const float inv_hi = 1.0f / l_hi;
    const int row_lo = qt * 128 + rb + r;
    const int row_hi = row_lo + 8;
#pragma unroll
    for (int nt = 0; nt < 8; ++nt) {
        const int gc = h * DK_ + nt * 8 + 2 * j;
        *(float2*)&g_ctx[(size_t)(b * S_ + row_lo) * D_ + gc] =
            make_float2(__uint_as_float(f2tf(o[nt][0] * inv_lo)),
                        __uint_as_float(f2tf(o[nt][1] * inv_lo)));
        *(float2*)&g_ctx[(size_t)(b * S_ + row_hi) * D_ + gc] =
            make_float2(__uint_as_float(f2tf(o[nt][2] * inv_hi)),
                        __uint_as_float(f2tf(o[nt][3] * inv_hi)));
    }
}

// ---------------------------------------------------------------------------
// LayerNorm over D=1024 with residual add: out = LN(g_proj + query)*g + b
// ---------------------------------------------------------------------------
__global__ __launch_bounds__(256)
void ln_resid(const float* __restrict__ resid, const float* __restrict__ gamma,
              const float* __restrict__ beta, float* __restrict__ out)
{
    __shared__ float rs[8], rq[8];
    const int row = blockIdx.x;
    const int tid = threadIdx.x;

    const float* xr = g_proj + (size_t)row * D_;
    const float* rr = resid  + (size_t)row * D_;

    float4 a = *(const float4*)&xr[tid * 4];
    float4 r = *(const float4*)&rr[tid * 4];
    float x0 = a.x + r.x, x1 = a.y + r.y, x2 = a.z + r.z, x3 = a.w + r.w;

    float s  = x0 + x1 + x2 + x3;
    float sq = x0 * x0 + x1 * x1 + x2 * x2 + x3 * x3;
#pragma unroll
    for (int off = 16; off >= 1; off >>= 1) {
        s  += __shfl_xor_sync(0xffffffffu, s,  off);
        sq += __shfl_xor_sync(0xffffffffu, sq, off);
    }
    const int wid = tid >> 5;
    if ((tid & 31) == 0) { rs[wid] = s; rq[wid] = sq; }
    __syncthreads();
    float tot = 0.0f, totq = 0.0f;
#pragma unroll
    for (int ww = 0; ww < 8; ++ww) { tot += rs[ww]; totq += rq[ww]; }

    const float mean = tot * (1.0f / D_);
    const float var  = totq * (1.0f / D_) - mean * mean;
    const float rstd = rsqrtf(var + 1e-5f);

    float4 g = *(const float4*)&gamma[tid * 4];
    float4 be = *(const float4*)&beta[tid * 4];
    float4 oo;
    oo.x = (x0 - mean) * rstd * g.x + be.x;
    oo.y = (x1 - mean) * rstd * g.y + be.y;
    oo.z = (x2 - mean) * rstd * g.z + be.z;
    oo.w = (x3 - mean) * rstd * g.w + be.w;
    *(float4*)&out[(size_t)row * D_ + tid * 4] = oo;
}

// ---------------------------------------------------------------------------
// kernel_launch
// ---------------------------------------------------------------------------
extern "C" void kernel_launch(void* const* d_in, const int* in_sizes, int n_in,
                              void* d_out, int out_size)
{
    (void)in_sizes; (void)n_in; (void)out_size;

    const float* query = (const float*)d_in[0];
    const float* key   = (const float*)d_in[1];
    const float* value = (const float*)d_in[2];
    const float* cplx  = (const float*)d_in[3];
    // d_in[4] = mask (bool tril) — deterministic, applied analytically
    const float* wq = (const float*)d_in[5];
    const float* bq = (const float*)d_in[6];
    const float* wk = (const float*)d_in[7];
    const float* bk = (const float*)d_in[8];
    const float* wv = (const float*)d_in[9];
    const float* bv = (const float*)d_in[10];
    const float* wo = (const float*)d_in[11];
    const float* bo = (const float*)d_in[12];
    const float* lng = (const float*)d_in[13];
    const float* lnb = (const float*)d_in[14];
    const float* cpen = (const float*)d_in[15];
    float* out = (float*)d_out;

    void *pQ, *pK, *pV, *pCtx, *pProj, *pRW, *pRX;
    cudaGetSymbolAddress(&pQ,    g_Q);
    cudaGetSymbolAddress(&pK,    g_K);
    cudaGetSymbolAddress(&pV,    g_V);
    cudaGetSymbolAddress(&pCtx,  g_ctx);
    cudaGetSymbolAddress(&pProj, g_proj);
    cudaGetSymbolAddress(&pRW,   g_rW);
    cudaGetSymbolAddress(&pRX,   g_rX);
    float* rW = (float*)pRW;
    float* rX = (float*)pRX;

    const int ATTN_SMEM = (128 * AP + 64 * AP + 64 * VP + 128 * AP) * 4; // 105472
    cudaFuncSetAttribute(attn_tc, cudaFuncAttributeMaxDynamicSharedMemorySize,
                         ATTN_SMEM);

    // ---- pre-round weights & activations to tf32 (one merged launch) ----
    const int NX = BS_ * D_;      // 4 M
    dim3 gr(NX / 1024, 1, 7);
    round_all<<<gr, 256>>>(wq, wk, wv, wo, query, key, value, rW, rX);

    // Q/K/V projections merged into one launch (dense wave packing)
    dim3 gg3(D_ / 128, BS_ / 128, 3);   // (8, 32, 3)
    gemm_qkv<<<gg3, 256>>>(rX, rW, bq, bk, bv,
                           (float*)pQ, (float*)pK, (float*)pV);

    // Flash attention -> g_ctx (tf32-rounded)
    dim3 ga(S_ / 128, B_ * H_);     // (16, 32)
    attn_tc<<<ga, 256, ATTN_SMEM>>>(cplx, cpen);

    // Output projection -> g_proj (exact fp32)
    const int NW = D_ * D_;
    dim3 gg(D_ / 128, BS_ / 128);   // (8, 32)
    gemm_tc0<<<gg, 256>>>((const float*)pCtx, rW + 3 * (size_t)NW, bo, (float*)pProj);

    // Residual + LayerNorm -> d_out
    ln_resid<<<BS_, 256>>>(query, lng, lnb, out);
}

// round 15
// speedup vs baseline: 2.2642x; 1.1075x over previous
#include <cuda_runtime.h>
#include <math.h>
#include <stdint.h>

// Problem constants
#define B_   2
#define S_   2048
#define D_   1024
#define H_   16
#define DK_  64
#define BS_  (B_ * S_)   // 4096

// ---------------------------------------------------------------------------
// Device scratch (no allocations allowed -> __device__ globals)
// ---------------------------------------------------------------------------
__device__ float g_Q[B_ * H_ * S_ * DK_];     // [B,H,S,DK]  (tf32-rounded)
__device__ float g_K[B_ * H_ * S_ * DK_];
__device__ float g_V[B_ * H_ * S_ * DK_];
__device__ float g_ctx[B_ * S_ * D_];         // [B,S,D]     (tf32-rounded)
__device__ float g_proj[B_ * S_ * D_];        // out-proj result (exact fp32)
__device__ float g_rW[4 * D_ * D_];           // rounded wq,wk,wv,wo
__device__ float g_rX[3 * BS_ * D_];          // rounded query,key,value

// ---------------------------------------------------------------------------
// tf32 + cp.async + ldmatrix helpers
// ---------------------------------------------------------------------------
__device__ __forceinline__ uint32_t f2tf(float f) {
    uint32_t u;
    asm("cvt.rna.tf32.f32 %0, %1;" : "=r"(u) : "f"(f));
    return u;
}
__device__ __forceinline__ uint4 f2tf4(float4 v) {
    uint4 u;
    u.x = f2tf(v.x); u.y = f2tf(v.y); u.z = f2tf(v.z); u.w = f2tf(v.w);
    return u;
}
__device__ __forceinline__ void cp16(uint32_t dst, const void* src) {
    asm volatile("cp.async.cg.shared.global [%0], [%1], 16;\n"
                 :: "r"(dst), "l"(src));
}
__device__ __forceinline__ void cp_commit() {
    asm volatile("cp.async.commit_group;\n");
}
template <int N>
__device__ __forceinline__ void cp_wait() {
    asm volatile("cp.async.wait_group %0;\n" :: "n"(N));
}
// ldmatrix x4: four 8-row x 16-byte matrices; lane groups 0-7/8-15/16-23/24-31
// supply the row addresses of matrices 0..3.
__device__ __forceinline__ void ldsm4(uint32_t& d0, uint32_t& d1,
                                      uint32_t& d2, uint32_t& d3, uint32_t addr) {
    asm volatile("ldmatrix.sync.aligned.m8n8.x4.shared.b16 {%0,%1,%2,%3}, [%4];"
                 : "=r"(d0), "=r"(d1), "=r"(d2), "=r"(d3) : "r"(addr));
}
// D(16x8,f32) += A(16x8,tf32,row) * B(8x8,tf32,col)
__device__ __forceinline__ void mma_tf32(float& d0, float& d1, float& d2, float& d3,
                                         uint32_t a0, uint32_t a1, uint32_t a2, uint32_t a3,
                                         uint32_t b0, uint32_t b1) {
    asm volatile(
        "mma.sync.aligned.m16n8k8.row.col.f32.tf32.tf32.f32 "
        "{%0,%1,%2,%3}, {%4,%5,%6,%7}, {%8,%9}, {%0,%1,%2,%3};\n"
        : "+f"(d0), "+f"(d1), "+f"(d2), "+f"(d3)
        : "r"(a0), "r"(a1), "r"(a2), "r"(a3), "r"(b0), "r"(b1));
}

// ---------------------------------------------------------------------------
// One merged tf32 rounding pass over all 7 tensors (z selects tensor).
// ---------------------------------------------------------------------------
__global__ void round_all(const float* __restrict__ wq, const float* __restrict__ wk,
                          const float* __restrict__ wv, const float* __restrict__ wo,
                          const float* __restrict__ xq, const float* __restrict__ xk,
                          const float* __restrict__ xv,
                          float* __restrict__ rW, float* __restrict__ rX)
{
    const int z = blockIdx.z;
    const int NW = D_ * D_;
    const int NX = BS_ * D_;
    const int n  = (z < 4) ? NW : NX;
    const int i  = (blockIdx.x * blockDim.x + threadIdx.x) * 4;
    if (i >= n) return;
    const float* src;
    float* dst;
    switch (z) {
        case 0: src = wq; dst = rW;                  break;
        case 1: src = wk; dst = rW + 1 * (size_t)NW; break;
        case 2: src = wv; dst = rW + 2 * (size_t)NW; break;
        case 3: src = wo; dst = rW + 3 * (size_t)NW; break;
        case 4: src = xq; dst = rX;                  break;
        case 5: src = xk; dst = rX + 1 * (size_t)NX; break;
        default: src = xv; dst = rX + 2 * (size_t)NX; break;
    }
    uint4 u = f2tf4(*(const float4*)(src + i));
    *(float4*)(dst + i) = make_float4(__uint_as_float(u.x), __uint_as_float(u.y),
                                      __uint_as_float(u.z), __uint_as_float(u.w));
}

// ---------------------------------------------------------------------------
// tf32 tensor-core GEMM body: Y[m][n] = sum_k A[m][k]*W[n][k] + bias[n]
// CTA 128x128, 256 thr, warp tile 64x32. k32 chunks, 2-stage cp.async.
// Fragment loads via ldmatrix: 6 LDSM per 16 HMMA (was 24 LDS.32).
// smem pitch 36 (rows of every 8x16B matrix land on distinct banks).
// ---------------------------------------------------------------------------
#define GP 36   // 32 data + 4 pad
#define GBUF (128 * GP * 4)   // one buffer in bytes

template <int MODE>
__device__ __forceinline__
void gemm_body(const float* __restrict__ A, const float* __restrict__ W,
               const float* __restrict__ bias, float* __restrict__ out,
               uint32_t (*As)[128 * GP], uint32_t (*Bs)[128 * GP])
{
    const int tid  = threadIdx.x;
    const int lane = tid & 31;
    const int w    = tid >> 5;
    const int wm   = w & 1;
    const int wn   = w >> 1;
    const int row0 = blockIdx.y * 128;
    const int col0 = blockIdx.x * 128;
    const int r = lane >> 2;
    const int j = lane & 3;

    const int lrow = tid & 127;
    const int lkq  = (tid >> 7) << 4;   // 0 or 16

    const float* Aptr = A + (size_t)(row0 + lrow) * D_ + lkq;
    const float* Wptr = W + (size_t)(col0 + lrow) * D_ + lkq;

    uint32_t sA[2], sB[2];
#pragma unroll
    for (int s = 0; s < 2; ++s) {
        sA[s] = (uint32_t)__cvta_generic_to_shared(&As[s][lrow * GP + lkq]);
        sB[s] = (uint32_t)__cvta_generic_to_shared(&Bs[s][lrow * GP + lkq]);
    }

    // ldmatrix lane addresses (byte, buffer 0)
    // A (x4 per mt): rows wm*64 + mt*16 + (lane&15), k-col (lane>>4)*4
    const uint32_t aBase = (uint32_t)__cvta_generic_to_shared(As) +
        (((wm * 64 + (lane & 15)) * GP + ((lane >> 4) << 2)) << 2);
    // B (x4 per nt-pair p): rows wn*32 + p*16 + ((lane>>4)&1)*8 + (lane&7),
    //                       k-col ((lane>>3)&1)*4
    const uint32_t bBase = (uint32_t)__cvta_generic_to_shared(Bs) +
        (((wn * 32 + (((lane >> 4) & 1) << 3) + (lane & 7)) * GP +
          (((lane >> 3) & 1) << 2)) << 2);

    float acc[4][4][4];
#pragma unroll
    for (int mt = 0; mt < 4; ++mt)
#pragma unroll
        for (int nt = 0; nt < 4; ++nt)
#pragma unroll
            for (int c = 0; c < 4; ++c) acc[mt][nt][c] = 0.0f;

    // prologue: stage chunk 0 into buffer 0
    {
#pragma unroll
        for (int q = 0; q < 4; ++q) {
            cp16(sA[0] + q * 16, Aptr + q * 4);
            cp16(sB[0] + q * 16, Wptr + q * 4);
        }
        cp_commit();
    }

    constexpr int TILES = D_ / 32;   // 32
    for (int t = 0; t < TILES; ++t) {
        cp_wait<0>();
        __syncthreads();   // staged chunk t visible; prior compute (t-1) done

        if (t + 1 < TILES) {
            const int nb = (t + 1) & 1;
            const float* a  = Aptr + (t + 1) * 32;
            const float* wv = Wptr + (t + 1) * 32;
#pragma unroll
            for (int q = 0; q < 4; ++q) {
                cp16(sA[nb] + q * 16, a + q * 4);
                cp16(sB[nb] + q * 16, wv + q * 4);
            }
            cp_commit();
        }

        const uint32_t aBuf = aBase + (t & 1) * GBUF;
        const uint32_t bBuf = bBase + (t & 1) * GBUF;
#pragma unroll
        for (int ss = 0; ss < 4; ++ss) {
            uint32_t af[4][4];
#pragma unroll
            for (int mt = 0; mt < 4; ++mt)
                ldsm4(af[mt][0], af[mt][1], af[mt][2], af[mt][3],
                      aBuf + mt * (16 * GP * 4) + ss * 32);
            uint32_t bf[4][2];
#pragma unroll
            for (int p = 0; p < 2; ++p)
                ldsm4(bf[2 * p][0], bf[2 * p][1], bf[2 * p + 1][0], bf[2 * p + 1][1],
                      bBuf + p * (16 * GP * 4) + ss * 32);
#pragma unroll
            for (int nt = 0; nt < 4; ++nt)
#pragma unroll
                for (int mt = 0; mt < 4; ++mt)
                    mma_tf32(acc[mt][nt][0], acc[mt][nt][1], acc[mt][nt][2], acc[mt][nt][3],
                             af[mt][0], af[mt][1], af[mt][2], af[mt][3],
                             bf[nt][0], bf[nt][1]);
        }
        // no trailing barrier: next iteration's top barrier orders buffer reuse
    }

    // epilogue
#pragma unroll
    for (int mt = 0; mt < 4; ++mt) {
        const int gr = row0 + wm * 64 + mt * 16 + r;
#pragma unroll
        for (int nt = 0; nt < 4; ++nt) {
            const int gc = col0 + wn * 32 + nt * 8 + 2 * j;
            const float2 bb = *(const float2*)&bias[gc];
            float2 v0 = make_float2(acc[mt][nt][0] + bb.x, acc[mt][nt][1] + bb.y);
            float2 v1 = make_float2(acc[mt][nt][2] + bb.x, acc[mt][nt][3] + bb.y);
            if (MODE == 0) {
                *(float2*)&out[(size_t)gr * D_ + gc]       = v0;
                *(float2*)&out[(size_t)(gr + 8) * D_ + gc] = v1;
            } else {
                // round to tf32 (consumed by attention MMAs)
                v0 = make_float2(__uint_as_float(f2tf(v0.x)), __uint_as_float(f2tf(v0.y)));
                v1 = make_float2(__uint_as_float(f2tf(v1.x)), __uint_as_float(f2tf(v1.y)));
                const int h  = gc >> 6;
                const int dk = gc & 63;
                const int b0i = gr >> 11, s0 = gr & (S_ - 1);
                const int gr1 = gr + 8;
                const int b1i = gr1 >> 11, s1 = gr1 & (S_ - 1);
                *(float2*)&out[(((size_t)(b0i * H_ + h) * S_) + s0) * DK_ + dk] = v0;
                *(float2*)&out[(((size_t)(b1i * H_ + h) * S_) + s1) * DK_ + dk] = v1;
            }
        }
    }
}

// wo projection: single GEMM, row-major fp32 out
__global__ __launch_bounds__(256, 2)
void gemm_tc0(const float* __restrict__ A, const float* __restrict__ W,
              const float* __restrict__ bias, float* __restrict__ out)
{
    __shared__ uint32_t As[2][128 * GP];
    __shared__ uint32_t Bs[2][128 * GP];
    gemm_body<0>(A, W, bias, out, As, Bs);
}

// QKV projections merged: blockIdx.z selects {q,k,v} -> dense wave packing
__global__ __launch_bounds__(256, 2)
void gemm_qkv(const float* __restrict__ X, const float* __restrict__ W4,
              const float* __restrict__ bq, const float* __restrict__ bk,
              const float* __restrict__ bv,
              float* __restrict__ oq, float* __restrict__ ok,
              float* __restrict__ ov)
{
    __shared__ uint32_t As[2][128 * GP];
    __shared__ uint32_t Bs[2][128 * GP];
    const int z = blockIdx.z;
    const size_t NX = (size_t)BS_ * D_;
    const size_t NW = (size_t)D_ * D_;
    const float* A    = X  + z * NX;
    const float* W    = W4 + z * NW;
    const float* bias = (z == 0) ? bq : (z == 1) ? bk : bv;
    float*       out  = (z == 0) ? oq : (z == 1) ? ok : ov;
    gemm_body<1>(A, W, bias, out, As, Bs);
}

// ---------------------------------------------------------------------------
// Flash attention, tf32 tensor cores, single-buffered K/V, 2 CTAs/SM.
// CTA 256 thr (8 warps), Q tile 128 rows, K tile 64 keys; warp = one m16 slice.
// smem (103 KB): Qs[128][68], Ks[64][68], Vs[64][72], Ps[128][68].
// Q/K/P fragments via ldmatrix (pitch 68: 17i mod 8 is a permutation ->
// conflict-free); V B-frags stay scalar LDS (pitch 72 would conflict).
// ---------------------------------------------------------------------------
#define AP 68
#define VP 72

__global__ __launch_bounds__(256, 2)
void attn_tc(const float* __restrict__ cplx, const float* __restrict__ cpen_p)
{
    extern __shared__ uint32_t smem[];
    uint32_t* Qs = smem;                 // 128*AP
    uint32_t* Ks = Qs + 128 * AP;        // 64*AP
    uint32_t* Vs = Ks + 64 * AP;         // 64*VP
    uint32_t* Ps = Vs + 64 * VP;         // 128*AP

    const int tid  = threadIdx.x;
    const int lane = tid & 31;
    const int w    = tid >> 5;
    const int r    = lane >> 2;
    const int j    = lane & 3;
    const int rb   = w * 16;              // warp row base (0..112)

    const int qt = (gridDim.x - 1) - blockIdx.x;   // heavy tiles first
    const int bh = blockIdx.y;
    const int b  = bh >> 4;
    const int h  = bh & 15;
    const float cpen = __ldg(cpen_p);

    const float* Qg = g_Q + (size_t)bh * S_ * DK_;
    const float* Kg = g_K + (size_t)bh * S_ * DK_;
    const float* Vg = g_V + (size_t)bh * S_ * DK_;

    // Q staging: 256 thr, each 32 floats of one row
    const int qrow  = tid >> 1;           // 0..127
    const int qhalf = (tid & 1) * 32;
    const uint32_t qdst = (uint32_t)__cvta_generic_to_shared(&Qs[qrow * AP + qhalf]);

    // K/V staging: 256 thr, each 16 floats of one row
    const int krow = tid >> 2;            // 0..63
    const int kq   = (tid & 3) * 16;
    const uint32_t kdst = (uint32_t)__cvta_generic_to_shared(&Ks[krow * AP + kq]);
    const uint32_t vdst = (uint32_t)__cvta_generic_to_shared(&Vs[krow * VP + kq]);

    // ldmatrix lane addresses (byte)
    // A-frags (Q and P): rows rb + (lane&15), k-col (lane>>4)*4
    const uint32_t qLm = (uint32_t)__cvta_generic_to_shared(Qs) +
        (((rb + (lane & 15)) * AP + ((lane >> 4) << 2)) << 2);
    const uint32_t pLm = (uint32_t)__cvta_generic_to_shared(Ps) +
        (((rb + (lane & 15)) * AP + ((lane >> 4) << 2)) << 2);
    // K B-frags (x4 per nt-pair): rows p*16 + ((lane>>4)&1)*8 + (lane&7),
    //                             k-col ((lane>>3)&1)*4
    const uint32_t kLm = (uint32_t)__cvta_generic_to_shared(Ks) +
        ((((((lane >> 4) & 1) << 3) + (lane & 7)) * AP +
          (((lane >> 3) & 1) << 2)) << 2);

    auto stage_kv = [&](int kt) {
        const float* ks = Kg + (size_t)(kt * 64 + krow) * DK_ + kq;
        const float* vs = Vg + (size_t)(kt * 64 + krow) * DK_ + kq;
#pragma unroll
        for (int q = 0; q < 4; ++q) {
            cp16(kdst + q * 16, ks + q * 4);
            cp16(vdst + q * 16, vs + q * 4);
        }
    };

    // prologue: Q tile + first K/V tile
    {
        const float* qs = Qg + (size_t)(qt * 128 + qrow) * DK_ + qhalf;
#pragma unroll
        for (int q = 0; q < 8; ++q) cp16(qdst + q * 16, qs + q * 4);
        stage_kv(0);
        cp_commit();
    }

    float o[8][4];
    float m_lo = -1e30f, m_hi = -1e30f, l_lo = 0.0f, l_hi = 0.0f;
#pragma unroll
    for (int nt = 0; nt < 8; ++nt)
#pragma unroll
        for (int c = 0; c < 4; ++c) o[nt][c] = 0.0f;

    const int nkt = 2 * qt + 2;
    for (int kt = 0; kt < nkt; ++kt) {
        cp_wait<0>();
        __syncthreads();   // staged K/V (+Q on iter 0) visible to all warps

        // ---- S = Q K^T  (warp: 16 rows x 64 keys) ----
        float s[8][4];
#pragma unroll
        for (int nt = 0; nt < 8; ++nt)
#pragma unroll
            for (int c = 0; c < 4; ++c) s[nt][c] = 0.0f;

#pragma unroll
        for (int ks = 0; ks < 8; ++ks) {
            uint32_t a0, a1, a2, a3;
            ldsm4(a0, a1, a2, a3, qLm + ks * 32);
            uint32_t kb[8][2];
#pragma unroll
            for (int p = 0; p < 4; ++p)
                ldsm4(kb[2 * p][0], kb[2 * p][1], kb[2 * p + 1][0], kb[2 * p + 1][1],
                      kLm + p * (16 * AP * 4) + ks * 32);
#pragma unroll
            for (int nt = 0; nt < 8; ++nt)
                mma_tf32(s[nt][0], s[nt][1], s[nt][2], s[nt][3],
                         a0, a1, a2, a3, kb[nt][0], kb[nt][1]);
        }

        // ---- scale + penalty + causal mask ----
        const int rowg_lo = qt * 128 + rb + r;
        const int rowg_hi = rowg_lo + 8;
#pragma unroll
        for (int nt = 0; nt < 8; ++nt) {
            const int colg = kt * 64 + nt * 8 + 2 * j;
            const float2 cv = *(const float2*)&cplx[b * S_ + colg];
            const float p0 = cpen * cv.x, p1 = cpen * cv.y;
            s[nt][0] = s[nt][0] * 0.125f - p0;
            s[nt][1] = s[nt][1] * 0.125f - p1;
            s[nt][2] = s[nt][2] * 0.125f - p0;
            s[nt][3] = s[nt][3] * 0.125f - p1;
            if (kt >= 2 * qt) {          // (possibly) diagonal k-tile
                if (colg     > rowg_lo) s[nt][0] = -1e9f;
                if (colg + 1 > rowg_lo) s[nt][1] = -1e9f;
                if (colg     > rowg_hi) s[nt][2] = -1e9f;
                if (colg + 1 > rowg_hi) s[nt][3] = -1e9f;
            }
        }

        // ---- online softmax ----
        float mx_lo = -1e30f, mx_hi = -1e30f;
#pragma unroll
        for (int nt = 0; nt < 8; ++nt) {
            mx_lo = fmaxf(mx_lo, fmaxf(s[nt][0], s[nt][1]));
            mx_hi = fmaxf(mx_hi, fmaxf(s[nt][2], s[nt][3]));
        }
        mx_lo = fmaxf(mx_lo, __shfl_xor_sync(0xffffffffu, mx_lo, 1));
        mx_lo = fmaxf(mx_lo, __shfl_xor_sync(0xffffffffu, mx_lo, 2));
        mx_hi = fmaxf(mx_hi, __shfl_xor_sync(0xffffffffu, mx_hi, 1));
        mx_hi = fmaxf(mx_hi, __shfl_xor_sync(0xffffffffu, mx_hi, 2));

        const float nm_lo = fmaxf(m_lo, mx_lo);
        const float nm_hi = fmaxf(m_hi, mx_hi);
        const float al_lo = __expf(m_lo - nm_lo);
        const float al_hi = __expf(m_hi - nm_hi);
        m_lo = nm_lo; m_hi = nm_hi;

        float sum_lo = 0.0f, sum_hi = 0.0f;
#pragma unroll
        for (int nt = 0; nt < 8; ++nt) {
            s[nt][0] = __expf(s[nt][0] - nm_lo);
            s[nt][1] = __expf(s[nt][1] - nm_lo);
            s[nt][2] = __expf(s[nt][2] - nm_hi);
            s[nt][3] = __expf(s[nt][3] - nm_hi);
            sum_lo += s[nt][0] + s[nt][1];
            sum_hi += s[nt][2] + s[nt][3];
            uint2 plo = make_uint2(f2tf(s[nt][0]), f2tf(s[nt][1]));
            uint2 phi = make_uint2(f2tf(s[nt][2]), f2tf(s[nt][3]));
            *(uint2*)&Ps[(rb + r) * AP + nt * 8 + 2 * j]     = plo;
            *(uint2*)&Ps[(rb + r + 8) * AP + nt * 8 + 2 * j] = phi;
        }
        sum_lo += __shfl_xor_sync(0xffffffffu, sum_lo, 1);
        sum_lo += __shfl_xor_sync(0xffffffffu, sum_lo, 2);
        sum_hi += __shfl_xor_sync(0xffffffffu, sum_hi, 1);
        sum_hi += __shfl_xor_sync(0xffffffffu, sum_hi, 2);
        l_lo = l_lo * al_lo + sum_lo;
        l_hi = l_hi * al_hi + sum_hi;

#pragma unroll
        for (int nt = 0; nt < 8; ++nt) {
            o[nt][0] *= al_lo; o[nt][1] *= al_lo;
            o[nt][2] *= al_hi; o[nt][3] *= al_hi;
        }
        __syncwarp();   // P (warp-private rows) visible within warp

        // ---- O += P V  (V row-major: B[k=key][n=d], pitch 72) ----
#pragma unroll
        for (int ks = 0; ks < 8; ++ks) {
            uint32_t a0, a1, a2, a3;
            ldsm4(a0, a1, a2, a3, pLm + ks * 32);
            const int krow0 = (ks * 8 + j) * VP;
            const int krow1 = (ks * 8 + j + 4) * VP;
#pragma unroll
            for (int nt = 0; nt < 8; ++nt) {
                uint32_t b0 = Vs[krow0 + nt * 8 + r];
                uint32_t b1 = Vs[krow1 + nt * 8 + r];
                mma_tf32(o[nt][0], o[nt][1], o[nt][2], o[nt][3], a0, a1, a2, a3, b0, b1);
            }
        }

        // all warps done reading Ks/Vs before restaging
        __syncthreads();
        if (kt + 1 < nkt) { stage_kv(kt + 1); cp_commit(); }
    }

    // ---- epilogue (ctx written tf32-rounded for the Wo GEMM) ----
    const float inv_lo = 1.0f / l_lo;
    const float inv_hi = 1.0f / l_hi;
    const int row_lo = qt * 128 + rb + r;
    const int row_hi = row_lo + 8;
#pragma unroll
    for (int nt = 0; nt < 8; ++nt) {
        const int gc = h * DK_ + nt * 8 + 2 * j;
        *(float2*)&g_ctx[(size_t)(b * S_ + row_lo) * D_ + gc] =
            make_float2(__uint_as_float(f2tf(o[nt][0] * inv_lo)),
                        __uint_as_float(f2tf(o[nt][1] * inv_lo)));
        *(float2*)&g_ctx[(size_t)(b * S_ + row_hi) * D_ + gc] =
            make_float2(__uint_as_float(f2tf(o[nt][2] * inv_hi)),
                        __uint_as_float(f2tf(o[nt][3] * inv_hi)));
    }
}

// ---------------------------------------------------------------------------
// LayerNorm over D=1024 with residual add: out = LN(g_proj + query)*g + b
// ---------------------------------------------------------------------------
__global__ __launch_bounds__(256)
void ln_resid(const float* __restrict__ resid, const float* __restrict__ gamma,
              const float* __restrict__ beta, float* __restrict__ out)
{
    __shared__ float rs[8], rq[8];
    const int row = blockIdx.x;
    const int tid = threadIdx.x;

    const float* xr = g_proj + (size_t)row * D_;
    const float* rr = resid  + (size_t)row * D_;

    float4 a = *(const float4*)&xr[tid * 4];
    float4 r = *(const float4*)&rr[tid * 4];
    float x0 = a.x + r.x, x1 = a.y + r.y, x2 = a.z + r.z, x3 = a.w + r.w;

    float s  = x0 + x1 + x2 + x3;
    float sq = x0 * x0 + x1 * x1 + x2 * x2 + x3 * x3;
#pragma unroll
    for (int off = 16; off >= 1; off >>= 1) {
        s  += __shfl_xor_sync(0xffffffffu, s,  off);
        sq += __shfl_xor_sync(0xffffffffu, sq, off);
    }
    const int wid = tid >> 5;
    if ((tid & 31) == 0) { rs[wid] = s; rq[wid] = sq; }
    __syncthreads();
    float tot = 0.0f, totq = 0.0f;
#pragma unroll
    for (int ww = 0; ww < 8; ++ww) { tot += rs[ww]; totq += rq[ww]; }

    const float mean = tot * (1.0f / D_);
    const float var  = totq * (1.0f / D_) - mean * mean;
    const float rstd = rsqrtf(var + 1e-5f);

    float4 g = *(const float4*)&gamma[tid * 4];
    float4 be = *(const float4*)&beta[tid * 4];
    float4 oo;
    oo.x = (x0 - mean) * rstd * g.x + be.x;
    oo.y = (x1 - mean) * rstd * g.y + be.y;
    oo.z = (x2 - mean) * rstd * g.z + be.z;
    oo.w = (x3 - mean) * rstd * g.w + be.w;
    *(float4*)&out[(size_t)row * D_ + tid * 4] = oo;
}

// ---------------------------------------------------------------------------
// kernel_launch
// ---------------------------------------------------------------------------
extern "C" void kernel_launch(void* const* d_in, const int* in_sizes, int n_in,
                              void* d_out, int out_size)
{
    (void)in_sizes; (void)n_in; (void)out_size;

    const float* query = (const float*)d_in[0];
    const float* key   = (const float*)d_in[1];
    const float* value = (const float*)d_in[2];
    const float* cplx  = (const float*)d_in[3];
    // d_in[4] = mask (bool tril) — deterministic, applied analytically
    const float* wq = (const float*)d_in[5];
    const float* bq = (const float*)d_in[6];
    const float* wk = (const float*)d_in[7];
    const float* bk = (const float*)d_in[8];
    const float* wv = (const float*)d_in[9];
    const float* bv = (const float*)d_in[10];
    const float* wo = (const float*)d_in[11];
    const float* bo = (const float*)d_in[12];
    const float* lng = (const float*)d_in[13];
    const float* lnb = (const float*)d_in[14];
    const float* cpen = (const float*)d_in[15];
    float* out = (float*)d_out;

    void *pQ, *pK, *pV, *pCtx, *pProj, *pRW, *pRX;
    cudaGetSymbolAddress(&pQ,    g_Q);
    cudaGetSymbolAddress(&pK,    g_K);
    cudaGetSymbolAddress(&pV,    g_V);
    cudaGetSymbolAddress(&pCtx,  g_ctx);
    cudaGetSymbolAddress(&pProj, g_proj);
    cudaGetSymbolAddress(&pRW,   g_rW);
    cudaGetSymbolAddress(&pRX,   g_rX);
    float* rW = (float*)pRW;
    float* rX = (float*)pRX;

    const int ATTN_SMEM = (128 * AP + 64 * AP + 64 * VP + 128 * AP) * 4; // 105472
    cudaFuncSetAttribute(attn_tc, cudaFuncAttributeMaxDynamicSharedMemorySize,
                         ATTN_SMEM);

    // ---- pre-round weights & activations to tf32 (one merged launch) ----
    const int NX = BS_ * D_;      // 4 M
    dim3 gr(NX / 1024, 1, 7);
    round_all<<<gr, 256>>>(wq, wk, wv, wo, query, key, value, rW, rX);

    // Q/K/V projections merged into one launch (dense wave packing)
    dim3 gg3(D_ / 128, BS_ / 128, 3);   // (8, 32, 3)
    gemm_qkv<<<gg3, 256>>>(rX, rW, bq, bk, bv,
                           (float*)pQ, (float*)pK, (float*)pV);

    // Flash attention -> g_ctx (tf32-rounded)
    dim3 ga(S_ / 128, B_ * H_);     // (16, 32)
    attn_tc<<<ga, 256, ATTN_SMEM>>>(cplx, cpen);

    // Output projection -> g_proj (exact fp32)
    const int NW = D_ * D_;
    dim3 gg(D_ / 128, BS_ / 128);   // (8, 32)
    gemm_tc0<<<gg, 256>>>((const float*)pCtx, rW + 3 * (size_t)NW, bo, (float*)pProj);

    // Residual + LayerNorm -> d_out
    ln_resid<<<BS_, 256>>>(query, lng, lnb, out);
}